// round 4
// baseline (speedup 1.0000x reference)
#include <cuda_runtime.h>
#include <math.h>

#define NN 20000
#define EE 640000
#define CC 128
#define EPSV 1e-5f

// -------------------- scratch (device globals; no allocation) --------------------
__device__ __align__(16) float  d_PQ[NN * 256];        // [node][0:128]=x@W1_top, [128:256]=x@W1_bot
__device__ __align__(16) float  d_W0[NN * CC];         // pass1: h0[j]*dinv[j]; pass2: g2[j]*dinv[j]
__device__ __align__(16) float  d_S1[NN * CC];
__device__ __align__(16) float  d_S2[NN * CC];
__device__ __align__(16) float  d_h1[(size_t)EE * CC]; // 327.68 MB
__device__ int    d_src[EE];
__device__ int    d_dst[EE];
__device__ int    d_is64;
__device__ int    d_cnt[NN];
__device__ int    d_start[NN + 1];
__device__ int    d_cursor[NN];
__device__ int    d_srcs[EE];
__device__ float  d_dinv[NN];
__device__ double d_sum[CC];
__device__ double d_sumsq[CC];
__device__ float  d_bnA[CC];                 // bn scale  (g * invstd)
__device__ float  d_bnB[CC];                 // bn offset (b - mean*scale)

// -------------------- dtype detect: int64 edge_index has zero high words --------------
__global__ void k_detect(const int* __restrict__ ei32) {
    if (threadIdx.x == 0) {
        int orv = 0;
        for (int i = 0; i < 128; i++) orv |= ei32[2 * i + 1];   // 1KB read, in-bounds either way
        d_is64 = (orv == 0) ? 1 : 0;
    }
}

// -------------------- convert edges to int32 src/dst --------------------
__global__ void k_convert(const int* __restrict__ ei32) {
    const int is64 = d_is64;
    int i = blockIdx.x * blockDim.x + threadIdx.x;
    int stride = gridDim.x * blockDim.x;
    for (int e = i; e < EE; e += stride) {
        if (is64) {
            d_src[e] = ei32[2 * e];                    // low word of ei64[e]
            d_dst[e] = ei32[2 * (EE + e)];             // low word of ei64[EE+e]
        } else {
            d_src[e] = ei32[e];
            d_dst[e] = ei32[EE + e];
        }
    }
}

// -------------------- zero counters --------------------
__global__ void k_zero() {
    int i = blockIdx.x * blockDim.x + threadIdx.x;
    int stride = gridDim.x * blockDim.x;
    for (int j = i; j < NN; j += stride) d_cnt[j] = 0;
    if (i < CC) { d_sum[i] = 0.0; d_sumsq[i] = 0.0; }
}

// -------------------- degree count --------------------
__global__ void k_deg() {
    int i = blockIdx.x * blockDim.x + threadIdx.x;
    if (i < EE) atomicAdd(&d_cnt[d_dst[i]], 1);
}

__global__ void k_dinv() {
    int i = blockIdx.x * blockDim.x + threadIdx.x;
    if (i < NN) d_dinv[i] = rsqrtf(1.0f + (float)d_cnt[i]);
}

// -------------------- exclusive scan over d_cnt (single block) --------------------
__global__ void k_scan() {
    __shared__ int sh[1024];
    __shared__ int carry_s;
    const int tid = threadIdx.x;
    if (tid == 0) carry_s = 0;
    __syncthreads();
    for (int base = 0; base < NN; base += 1024) {
        int idx = base + tid;
        int v = (idx < NN) ? d_cnt[idx] : 0;
        sh[tid] = v;
        __syncthreads();
        for (int o = 1; o < 1024; o <<= 1) {
            int t = (tid >= o) ? sh[tid - o] : 0;
            __syncthreads();
            sh[tid] += t;
            __syncthreads();
        }
        int excl = sh[tid] - v + carry_s;
        if (idx < NN) { d_start[idx] = excl; d_cursor[idx] = excl; }
        __syncthreads();
        if (tid == 0) carry_s += sh[1023];
        __syncthreads();
    }
    if (tid == 0) d_start[NN] = carry_s;
}

// -------------------- bin edges by dst --------------------
__global__ void k_fill() {
    int e = blockIdx.x * blockDim.x + threadIdx.x;
    if (e < EE) {
        int d = d_dst[e];
        int pos = atomicAdd(&d_cursor[d], 1);
        d_srcs[pos] = d_src[e];
    }
}

// -------------------- PQ = x @ [W1_top | W1_bot]  (M=20000, N=128 per half, K=128) ----
__global__ __launch_bounds__(256) void k_pq(const float* __restrict__ x,
                                            const float* __restrict__ W1) {
    __shared__ __align__(16) float As[16][128];
    __shared__ __align__(16) float Bs[16][128];
    const int tid = threadIdx.x;
    const int tx = tid & 15, ty = tid >> 4;
    const int row0 = blockIdx.x * 128;
    const int half = blockIdx.y;            // 0 -> W1 rows 0..127, 1 -> rows 128..255
    const int m = tid & 127;
    const int kh = (tid >> 7) * 8;
    const int kb = tid >> 4;
    const int n0 = (tid & 15) * 8;

    float acc[8][8];
#pragma unroll
    for (int i = 0; i < 8; i++)
#pragma unroll
        for (int j = 0; j < 8; j++) acc[i][j] = 0.f;

    for (int k0 = 0; k0 < 128; k0 += 16) {
        float4 a0 = make_float4(0, 0, 0, 0), a1 = make_float4(0, 0, 0, 0);
        int rr = row0 + m;
        if (rr < NN) {
            const float4* ap = reinterpret_cast<const float4*>(x + (size_t)rr * 128 + k0 + kh);
            a0 = ap[0]; a1 = ap[1];
        }
        As[kh + 0][m] = a0.x; As[kh + 1][m] = a0.y; As[kh + 2][m] = a0.z; As[kh + 3][m] = a0.w;
        As[kh + 4][m] = a1.x; As[kh + 5][m] = a1.y; As[kh + 6][m] = a1.z; As[kh + 7][m] = a1.w;

        const float4* bp = reinterpret_cast<const float4*>(
            W1 + (size_t)(half * 128 + k0 + kb) * 128 + n0);
        float4 b0 = bp[0], b1 = bp[1];
        *reinterpret_cast<float4*>(&Bs[kb][n0]) = b0;
        *reinterpret_cast<float4*>(&Bs[kb][n0 + 4]) = b1;
        __syncthreads();
#pragma unroll
        for (int k = 0; k < 16; k++) {
            float a[8], b[8];
            *reinterpret_cast<float4*>(a)     = *reinterpret_cast<const float4*>(&As[k][ty * 8]);
            *reinterpret_cast<float4*>(a + 4) = *reinterpret_cast<const float4*>(&As[k][ty * 8 + 4]);
            *reinterpret_cast<float4*>(b)     = *reinterpret_cast<const float4*>(&Bs[k][tx * 8]);
            *reinterpret_cast<float4*>(b + 4) = *reinterpret_cast<const float4*>(&Bs[k][tx * 8 + 4]);
#pragma unroll
            for (int i = 0; i < 8; i++)
#pragma unroll
                for (int j = 0; j < 8; j++) acc[i][j] = fmaf(a[i], b[j], acc[i][j]);
        }
        __syncthreads();
    }
#pragma unroll
    for (int i = 0; i < 8; i++) {
        int r = row0 + ty * 8 + i;
        if (r < NN) {
            float4 o0 = make_float4(acc[i][0], acc[i][1], acc[i][2], acc[i][3]);
            float4 o1 = make_float4(acc[i][4], acc[i][5], acc[i][6], acc[i][7]);
            float* dst = &d_PQ[(size_t)r * 256 + half * 128 + tx * 8];
            reinterpret_cast<float4*>(dst)[0] = o0;
            reinterpret_cast<float4*>(dst)[1] = o1;
        }
    }
}

// -------------------- W0[j] = (P[src_j] + Q[dst_j]) * dinv[j], j<NN --------------------
__global__ void k_w0() {
    int j = blockIdx.x;
    int c = threadIdx.x;
    int s = d_src[j];
    int d = d_dst[j];
    float dv = d_dinv[j];
    d_W0[j * CC + c] = (d_PQ[s * 256 + c] + d_PQ[d * 256 + 128 + c]) * dv;
}

// -------------------- gather aggregation: S[d] = sum_{e: dst(e)=d} W0[src(e)] ---------
template <int PASS>
__global__ void k_gather() {
    float* S = (PASS == 0) ? d_S1 : d_S2;
    const int d = blockIdx.x;
    const int c = threadIdx.x;
    const int p0 = d_start[d], p1 = d_start[d + 1];
    float a0 = 0.f, a1 = 0.f, a2 = 0.f, a3 = 0.f;
    int p = p0;
    for (; p + 4 <= p1; p += 4) {
        int s0 = d_srcs[p], s1 = d_srcs[p + 1], s2 = d_srcs[p + 2], s3 = d_srcs[p + 3];
        a0 += d_W0[s0 * CC + c];
        a1 += d_W0[s1 * CC + c];
        a2 += d_W0[s2 * CC + c];
        a3 += d_W0[s3 * CC + c];
    }
    for (; p < p1; p++) a0 += d_W0[d_srcs[p] * CC + c];
    S[d * CC + c] = (a0 + a1) + (a2 + a3);
}

// -------------------- h1 = b1 + h0*dinv^2 + dinv*S1; BN stats --------------------
__global__ void k_h1(const float* __restrict__ b1) {
    __shared__ int ssrc[512];
    __shared__ int sdst[512];
    const int c = threadIdx.x;
    const int r0 = blockIdx.x * 512;
    for (int i = c; i < 512; i += 128) {
        ssrc[i] = d_src[r0 + i];
        sdst[i] = d_dst[r0 + i];
    }
    __syncthreads();
    const float b1c = b1[c];
    float s = 0.f, ss = 0.f;
#pragma unroll 4
    for (int i = 0; i < 512; i++) {
        int r = r0 + i;
        float h0 = d_PQ[ssrc[i] * 256 + c] + d_PQ[sdst[i] * 256 + 128 + c];
        float h;
        if (r < NN) {
            float dv = d_dinv[r];
            h = fmaf(h0, dv * dv, fmaf(dv, d_S1[r * CC + c], b1c));
        } else {
            h = h0 + b1c;
        }
        d_h1[(size_t)r * CC + c] = h;
        s += h; ss += h * h;
    }
    atomicAdd(&d_sum[c], (double)s);
    atomicAdd(&d_sumsq[c], (double)ss);
}

// -------------------- BN finalize --------------------
__global__ void k_bnfinal(const float* __restrict__ bn_g, const float* __restrict__ bn_b) {
    int c = threadIdx.x;
    double mu = d_sum[c] / (double)EE;
    double var = d_sumsq[c] / (double)EE - mu * mu;
    float rstd = rsqrtf((float)var + EPSV);
    float a = bn_g[c] * rstd;
    d_bnA[c] = a;
    d_bnB[c] = fmaf(-(float)mu, a, bn_b[c]);
}

// -------------------- g2small: rows<NN of relu(bn(h1)) @ W2, scaled by dinv ----------
__global__ __launch_bounds__(256) void k_g2small(const float* __restrict__ W2) {
    __shared__ __align__(16) float As[16][128];
    __shared__ __align__(16) float Bs[16][128];
    const int tid = threadIdx.x;
    const int tx = tid & 15, ty = tid >> 4;
    const int row0 = blockIdx.x * 128;
    const int m = tid & 127;
    const int kh = (tid >> 7) * 8;
    const int kb = tid >> 4;
    const int n0 = (tid & 15) * 8;

    float acc[8][8];
#pragma unroll
    for (int i = 0; i < 8; i++)
#pragma unroll
        for (int j = 0; j < 8; j++) acc[i][j] = 0.f;

    for (int k0 = 0; k0 < 128; k0 += 16) {
        int rr = row0 + m;
        float av[8] = {0, 0, 0, 0, 0, 0, 0, 0};
        if (rr < NN) {
            const float4* ap = reinterpret_cast<const float4*>(
                &d_h1[(size_t)rr * CC + k0 + kh]);
            float4 a0 = ap[0], a1 = ap[1];
            av[0] = a0.x; av[1] = a0.y; av[2] = a0.z; av[3] = a0.w;
            av[4] = a1.x; av[5] = a1.y; av[6] = a1.z; av[7] = a1.w;
        }
#pragma unroll
        for (int t = 0; t < 8; t++) {
            int kk = k0 + kh + t;
            As[kh + t][m] = fmaxf(fmaf(av[t], d_bnA[kk], d_bnB[kk]), 0.f);
        }
        const float4* bp = reinterpret_cast<const float4*>(
            W2 + (size_t)(k0 + kb) * 128 + n0);
        float4 b0 = bp[0], b1 = bp[1];
        *reinterpret_cast<float4*>(&Bs[kb][n0]) = b0;
        *reinterpret_cast<float4*>(&Bs[kb][n0 + 4]) = b1;
        __syncthreads();
#pragma unroll
        for (int k = 0; k < 16; k++) {
            float a[8], b[8];
            *reinterpret_cast<float4*>(a)     = *reinterpret_cast<const float4*>(&As[k][ty * 8]);
            *reinterpret_cast<float4*>(a + 4) = *reinterpret_cast<const float4*>(&As[k][ty * 8 + 4]);
            *reinterpret_cast<float4*>(b)     = *reinterpret_cast<const float4*>(&Bs[k][tx * 8]);
            *reinterpret_cast<float4*>(b + 4) = *reinterpret_cast<const float4*>(&Bs[k][tx * 8 + 4]);
#pragma unroll
            for (int i = 0; i < 8; i++)
#pragma unroll
                for (int j = 0; j < 8; j++) acc[i][j] = fmaf(a[i], b[j], acc[i][j]);
        }
        __syncthreads();
    }
#pragma unroll
    for (int i = 0; i < 8; i++) {
        int r = row0 + ty * 8 + i;
        if (r < NN) {
            float dv = d_dinv[r];
            float4 o0 = make_float4(acc[i][0] * dv, acc[i][1] * dv, acc[i][2] * dv, acc[i][3] * dv);
            float4 o1 = make_float4(acc[i][4] * dv, acc[i][5] * dv, acc[i][6] * dv, acc[i][7] * dv);
            float* dst = &d_W0[r * CC + tx * 8];
            reinterpret_cast<float4*>(dst)[0] = o0;
            reinterpret_cast<float4*>(dst)[1] = o1;
        }
    }
}

// -------------------- final fused: GEMM2 + GCN combine + LN + ReLU + W3 dot ----------
__global__ __launch_bounds__(256) void k_final(const float* __restrict__ W2,
                                               const float* __restrict__ b2,
                                               const float* __restrict__ lng,
                                               const float* __restrict__ lnb,
                                               const float* __restrict__ W3,
                                               const float* __restrict__ b3,
                                               float* __restrict__ out) {
    __shared__ __align__(16) float As[16][128];
    __shared__ __align__(16) float Bs[16][128];
    const int tid = threadIdx.x;
    const int tx = tid & 15, ty = tid >> 4;
    const int row0 = blockIdx.x * 128;     // EE = 5000 * 128 exactly
    const int m = tid & 127;
    const int kh = (tid >> 7) * 8;
    const int kb = tid >> 4;
    const int n0 = (tid & 15) * 8;

    float acc[8][8];
#pragma unroll
    for (int i = 0; i < 8; i++)
#pragma unroll
        for (int j = 0; j < 8; j++) acc[i][j] = 0.f;

    for (int k0 = 0; k0 < 128; k0 += 16) {
        const float4* ap = reinterpret_cast<const float4*>(
            &d_h1[(size_t)(row0 + m) * CC + k0 + kh]);
        float4 a0 = ap[0], a1 = ap[1];
        float av[8] = {a0.x, a0.y, a0.z, a0.w, a1.x, a1.y, a1.z, a1.w};
#pragma unroll
        for (int t = 0; t < 8; t++) {
            int kk = k0 + kh + t;
            As[kh + t][m] = fmaxf(fmaf(av[t], d_bnA[kk], d_bnB[kk]), 0.f);
        }
        const float4* bp = reinterpret_cast<const float4*>(
            W2 + (size_t)(k0 + kb) * 128 + n0);
        float4 b0 = bp[0], b1 = bp[1];
        *reinterpret_cast<float4*>(&Bs[kb][n0]) = b0;
        *reinterpret_cast<float4*>(&Bs[kb][n0 + 4]) = b1;
        __syncthreads();
#pragma unroll
        for (int k = 0; k < 16; k++) {
            float a[8], b[8];
            *reinterpret_cast<float4*>(a)     = *reinterpret_cast<const float4*>(&As[k][ty * 8]);
            *reinterpret_cast<float4*>(a + 4) = *reinterpret_cast<const float4*>(&As[k][ty * 8 + 4]);
            *reinterpret_cast<float4*>(b)     = *reinterpret_cast<const float4*>(&Bs[k][tx * 8]);
            *reinterpret_cast<float4*>(b + 4) = *reinterpret_cast<const float4*>(&Bs[k][tx * 8 + 4]);
#pragma unroll
            for (int i = 0; i < 8; i++)
#pragma unroll
                for (int j = 0; j < 8; j++) acc[i][j] = fmaf(a[i], b[j], acc[i][j]);
        }
        __syncthreads();
    }

    // per-column constants
    float b2c[8], lgc[8], lbc[8], w3c[8];
#pragma unroll
    for (int j = 0; j < 8; j++) {
        int cj = tx * 8 + j;
        b2c[j] = b2[cj]; lgc[j] = lng[cj]; lbc[j] = lnb[cj]; w3c[j] = W3[cj];
    }
    const float b3v = b3[0];

#pragma unroll
    for (int i = 0; i < 8; i++) {
        int r = row0 + ty * 8 + i;
        float dv = 1.f, d2 = 1.f;
        float s2v[8] = {0, 0, 0, 0, 0, 0, 0, 0};
        if (r < NN) {
            dv = d_dinv[r];
            d2 = dv * dv;
            const float4* sp = reinterpret_cast<const float4*>(&d_S2[r * CC + tx * 8]);
            float4 t0 = sp[0], t1 = sp[1];
            s2v[0] = t0.x; s2v[1] = t0.y; s2v[2] = t0.z; s2v[3] = t0.w;
            s2v[4] = t1.x; s2v[5] = t1.y; s2v[6] = t1.z; s2v[7] = t1.w;
        }
        float val[8], s = 0.f, ss = 0.f;
#pragma unroll
        for (int j = 0; j < 8; j++) {
            float v = fmaf(acc[i][j], d2, fmaf(dv, s2v[j], b2c[j]));
            val[j] = v; s += v; ss += v * v;
        }
#pragma unroll
        for (int o = 8; o; o >>= 1) {
            s  += __shfl_xor_sync(0xffffffffu, s,  o, 16);
            ss += __shfl_xor_sync(0xffffffffu, ss, o, 16);
        }
        float mu = s * (1.f / 128.f);
        float var = ss * (1.f / 128.f) - mu * mu;
        float rstd = rsqrtf(var + EPSV);
        float dot = 0.f;
#pragma unroll
        for (int j = 0; j < 8; j++) {
            float y = fmaf((val[j] - mu) * rstd, lgc[j], lbc[j]);
            y = fmaxf(y, 0.f);
            dot = fmaf(y, w3c[j], dot);
        }
#pragma unroll
        for (int o = 8; o; o >>= 1) dot += __shfl_xor_sync(0xffffffffu, dot, o, 16);
        if (tx == 0) out[r] = dot + b3v;
    }
}

// -------------------- launch --------------------
extern "C" void kernel_launch(void* const* d_in, const int* in_sizes, int n_in,
                              void* d_out, int out_size) {
    const float* x    = (const float*)d_in[0];
    const int*   ei32 = (const int*)d_in[1];      // raw view; dtype resolved on device
    const float* W1   = (const float*)d_in[2];
    const float* b1   = (const float*)d_in[3];
    const float* bn_g = (const float*)d_in[4];
    const float* bn_b = (const float*)d_in[5];
    const float* W2   = (const float*)d_in[6];
    const float* b2   = (const float*)d_in[7];
    const float* ln_g = (const float*)d_in[8];
    const float* ln_b = (const float*)d_in[9];
    const float* W3   = (const float*)d_in[10];
    const float* b3   = (const float*)d_in[11];
    float* out = (float*)d_out;

    k_detect<<<1, 32>>>(ei32);
    k_convert<<<1024, 256>>>(ei32);
    k_zero<<<256, 256>>>();
    k_deg<<<(EE + 255) / 256, 256>>>();
    k_dinv<<<(NN + 255) / 256, 256>>>();
    k_scan<<<1, 1024>>>();
    k_fill<<<(EE + 255) / 256, 256>>>();
    k_pq<<<dim3((NN + 127) / 128, 2), 256>>>(x, W1);
    k_w0<<<NN, CC>>>();
    k_gather<0><<<NN, CC>>>();
    k_h1<<<EE / 512, CC>>>(b1);
    k_bnfinal<<<1, CC>>>(bn_g, bn_b);
    k_g2small<<<(NN + 127) / 128, 256>>>(W2);
    k_gather<1><<<NN, CC>>>();
    k_final<<<EE / 128, 256>>>(W2, b2, ln_g, ln_b, W3, b3, out);
}

// round 5
// speedup vs baseline: 1.0890x; 1.0890x over previous
#include <cuda_runtime.h>
#include <math.h>

#define NN 20000
#define EE 640000
#define CC 128
#define EPSV 1e-5f

// -------------------- scratch (device globals; no allocation) --------------------
__device__ __align__(16) float  d_PQ[NN * 256];   // [node][0:128]=x@W1_top, [128:256]=x@W1_bot (20MB, L2-resident)
__device__ __align__(16) float  d_W0[NN * CC];    // pass1: h0[j]*dinv[j]; pass2: g2[j]*dinv[j]
__device__ __align__(16) float  d_S1[NN * CC];
__device__ __align__(16) float  d_S2[NN * CC];
__device__ int    d_src[EE];
__device__ int    d_dst[EE];
__device__ int    d_is64;
__device__ int    d_cnt[NN];
__device__ int    d_start[NN + 1];
__device__ int    d_cursor[NN];
__device__ int    d_srcs[EE];
__device__ float  d_dinv[NN];
__device__ double d_sum[CC];
__device__ double d_sumsq[CC];
__device__ float  d_bnA[CC];                 // bn scale (g * invstd)
__device__ float  d_bnB[CC];                 // bn offset for raw h (incl. b1 fold)  : used by GEMMs
__device__ float  d_bnBr[CC];                // bn offset w/o b1 fold (unused by GEMMs)

// -------------------- dtype detect: int64 edge_index has zero high words --------------
__global__ void k_detect(const int* __restrict__ ei32) {
    if (threadIdx.x == 0) {
        int orv = 0;
        for (int i = 0; i < 128; i++) orv |= ei32[2 * i + 1];
        d_is64 = (orv == 0) ? 1 : 0;
    }
}

// -------------------- zero counters --------------------
__global__ void k_zero() {
    int i = blockIdx.x * blockDim.x + threadIdx.x;
    int stride = gridDim.x * blockDim.x;
    for (int j = i; j < NN; j += stride) d_cnt[j] = 0;
    if (i < CC) { d_sum[i] = 0.0; d_sumsq[i] = 0.0; }
}

// -------------------- convert edges to int32 src/dst + degree count --------------------
__global__ void k_convert(const int* __restrict__ ei32) {
    const int is64 = d_is64;
    int i = blockIdx.x * blockDim.x + threadIdx.x;
    int stride = gridDim.x * blockDim.x;
    for (int e = i; e < EE; e += stride) {
        int s, d;
        if (is64) {
            s = ei32[2 * e];
            d = ei32[2 * (EE + e)];
        } else {
            s = ei32[e];
            d = ei32[EE + e];
        }
        d_src[e] = s;
        d_dst[e] = d;
        atomicAdd(&d_cnt[d], 1);
    }
}

__global__ void k_dinv() {
    int i = blockIdx.x * blockDim.x + threadIdx.x;
    if (i < NN) d_dinv[i] = rsqrtf(1.0f + (float)d_cnt[i]);
}

// -------------------- exclusive scan over d_cnt (single block) --------------------
__global__ void k_scan() {
    __shared__ int sh[1024];
    __shared__ int carry_s;
    const int tid = threadIdx.x;
    if (tid == 0) carry_s = 0;
    __syncthreads();
    for (int base = 0; base < NN; base += 1024) {
        int idx = base + tid;
        int v = (idx < NN) ? d_cnt[idx] : 0;
        sh[tid] = v;
        __syncthreads();
        for (int o = 1; o < 1024; o <<= 1) {
            int t = (tid >= o) ? sh[tid - o] : 0;
            __syncthreads();
            sh[tid] += t;
            __syncthreads();
        }
        int excl = sh[tid] - v + carry_s;
        if (idx < NN) { d_start[idx] = excl; d_cursor[idx] = excl; }
        __syncthreads();
        if (tid == 0) carry_s += sh[1023];
        __syncthreads();
    }
    if (tid == 0) d_start[NN] = carry_s;
}

// -------------------- bin edges by dst --------------------
__global__ void k_fill() {
    int e = blockIdx.x * blockDim.x + threadIdx.x;
    if (e < EE) {
        int d = d_dst[e];
        int pos = atomicAdd(&d_cursor[d], 1);
        d_srcs[pos] = d_src[e];
    }
}

// -------------------- PQ = x @ [W1_top | W1_bot] --------------------
__global__ __launch_bounds__(256) void k_pq(const float* __restrict__ x,
                                            const float* __restrict__ W1) {
    __shared__ __align__(16) float As[16][128];
    __shared__ __align__(16) float Bs[16][128];
    const int tid = threadIdx.x;
    const int tx = tid & 15, ty = tid >> 4;
    const int row0 = blockIdx.x * 128;
    const int half = blockIdx.y;
    const int m = tid & 127;
    const int kh = (tid >> 7) * 8;
    const int kb = tid >> 4;
    const int n0 = (tid & 15) * 8;

    float acc[8][8];
#pragma unroll
    for (int i = 0; i < 8; i++)
#pragma unroll
        for (int j = 0; j < 8; j++) acc[i][j] = 0.f;

    for (int k0 = 0; k0 < 128; k0 += 16) {
        float4 a0 = make_float4(0, 0, 0, 0), a1 = make_float4(0, 0, 0, 0);
        int rr = row0 + m;
        if (rr < NN) {
            const float4* ap = reinterpret_cast<const float4*>(x + (size_t)rr * 128 + k0 + kh);
            a0 = ap[0]; a1 = ap[1];
        }
        As[kh + 0][m] = a0.x; As[kh + 1][m] = a0.y; As[kh + 2][m] = a0.z; As[kh + 3][m] = a0.w;
        As[kh + 4][m] = a1.x; As[kh + 5][m] = a1.y; As[kh + 6][m] = a1.z; As[kh + 7][m] = a1.w;

        const float4* bp = reinterpret_cast<const float4*>(
            W1 + (size_t)(half * 128 + k0 + kb) * 128 + n0);
        float4 b0 = bp[0], b1v = bp[1];
        *reinterpret_cast<float4*>(&Bs[kb][n0]) = b0;
        *reinterpret_cast<float4*>(&Bs[kb][n0 + 4]) = b1v;
        __syncthreads();
#pragma unroll
        for (int k = 0; k < 16; k++) {
            float a[8], b[8];
            *reinterpret_cast<float4*>(a)     = *reinterpret_cast<const float4*>(&As[k][ty * 8]);
            *reinterpret_cast<float4*>(a + 4) = *reinterpret_cast<const float4*>(&As[k][ty * 8 + 4]);
            *reinterpret_cast<float4*>(b)     = *reinterpret_cast<const float4*>(&Bs[k][tx * 8]);
            *reinterpret_cast<float4*>(b + 4) = *reinterpret_cast<const float4*>(&Bs[k][tx * 8 + 4]);
#pragma unroll
            for (int i = 0; i < 8; i++)
#pragma unroll
                for (int j = 0; j < 8; j++) acc[i][j] = fmaf(a[i], b[j], acc[i][j]);
        }
        __syncthreads();
    }
#pragma unroll
    for (int i = 0; i < 8; i++) {
        int r = row0 + ty * 8 + i;
        if (r < NN) {
            float4 o0 = make_float4(acc[i][0], acc[i][1], acc[i][2], acc[i][3]);
            float4 o1 = make_float4(acc[i][4], acc[i][5], acc[i][6], acc[i][7]);
            float* dst = &d_PQ[(size_t)r * 256 + half * 128 + tx * 8];
            reinterpret_cast<float4*>(dst)[0] = o0;
            reinterpret_cast<float4*>(dst)[1] = o1;
        }
    }
}

// -------------------- W0[j] = (P[src_j] + Q[dst_j]) * dinv[j], j<NN --------------------
__global__ void k_w0() {
    int j = blockIdx.x;
    int c = threadIdx.x;
    int s = d_src[j];
    int d = d_dst[j];
    float dv = d_dinv[j];
    d_W0[j * CC + c] = (d_PQ[s * 256 + c] + d_PQ[d * 256 + 128 + c]) * dv;
}

// -------------------- gather aggregation: S[d] = sum_{e: dst(e)=d} W0[src(e)] ---------
template <int PASS>
__global__ void k_gather() {
    float* S = (PASS == 0) ? d_S1 : d_S2;
    const int d = blockIdx.x;
    const int c = threadIdx.x;
    const int p0 = d_start[d], p1 = d_start[d + 1];
    float a0 = 0.f, a1 = 0.f, a2 = 0.f, a3 = 0.f;
    int p = p0;
    for (; p + 4 <= p1; p += 4) {
        int s0 = d_srcs[p], s1 = d_srcs[p + 1], s2 = d_srcs[p + 2], s3 = d_srcs[p + 3];
        a0 += d_W0[s0 * CC + c];
        a1 += d_W0[s1 * CC + c];
        a2 += d_W0[s2 * CC + c];
        a3 += d_W0[s3 * CC + c];
    }
    for (; p < p1; p++) a0 += d_W0[d_srcs[p] * CC + c];
    S[d * CC + c] = (a0 + a1) + (a2 + a3);
}

// -------------------- BN stats over virtual h1 (no materialization) --------------------
__global__ void k_stats(const float* __restrict__ b1) {
    __shared__ int ssrc[512];
    __shared__ int sdst[512];
    const int c = threadIdx.x;
    const int r0 = blockIdx.x * 512;
    for (int i = c; i < 512; i += 128) {
        ssrc[i] = d_src[r0 + i];
        sdst[i] = d_dst[r0 + i];
    }
    __syncthreads();
    const float b1c = b1[c];
    float s = 0.f, ss = 0.f;
#pragma unroll 4
    for (int i = 0; i < 512; i++) {
        int r = r0 + i;
        float h0 = d_PQ[ssrc[i] * 256 + c] + d_PQ[sdst[i] * 256 + 128 + c];
        float h;
        if (r < NN) {
            float dv = d_dinv[r];
            h = fmaf(h0, dv * dv, fmaf(dv, d_S1[r * CC + c], b1c));
        } else {
            h = h0 + b1c;
        }
        s += h; ss += h * h;
    }
    atomicAdd(&d_sum[c], (double)s);
    atomicAdd(&d_sumsq[c], (double)ss);
}

// -------------------- BN finalize (folds b1 into offset) --------------------
__global__ void k_bnfinal(const float* __restrict__ bn_g, const float* __restrict__ bn_b,
                          const float* __restrict__ b1) {
    int c = threadIdx.x;
    double mu = d_sum[c] / (double)EE;
    double var = d_sumsq[c] / (double)EE - mu * mu;
    float rstd = rsqrtf((float)var + EPSV);
    float a = bn_g[c] * rstd;
    d_bnA[c] = a;
    float boff = fmaf(-(float)mu, a, bn_b[c]);
    d_bnBr[c] = boff;
    d_bnB[c]  = fmaf(b1[c], a, boff);   // applies to h WITHOUT b1 added
}

// ========== shared A-tile builder: As[k][m] = relu(bnA*h + bnB2), h from PQ gathers ====
// Caller provides ssrc/sdst/sdv (per-row), sA/sB (per-col bn const), k0, kh, m.
__device__ __forceinline__ void build_a_tile(
    float As[16][128], const int* ssrc, const int* sdst, const float* sdv,
    const float* sA, const float* sB, int row0, int m, int kh, int k0) {
    const int s = ssrc[m], d = sdst[m];
    const float dv = sdv[m];
    const float4* pp = reinterpret_cast<const float4*>(&d_PQ[s * 256 + k0 + kh]);
    float4 p0 = pp[0], p1 = pp[1];
    const float4* qp = reinterpret_cast<const float4*>(&d_PQ[d * 256 + 128 + k0 + kh]);
    float4 q0 = qp[0], q1 = qp[1];
    float h[8] = {p0.x + q0.x, p0.y + q0.y, p0.z + q0.z, p0.w + q0.w,
                  p1.x + q1.x, p1.y + q1.y, p1.z + q1.z, p1.w + q1.w};
    if (dv >= 0.f) {
        const float4* s1p = reinterpret_cast<const float4*>(&d_S1[(row0 + m) * CC + k0 + kh]);
        float4 t0 = s1p[0], t1 = s1p[1];
        float sv[8] = {t0.x, t0.y, t0.z, t0.w, t1.x, t1.y, t1.z, t1.w};
        float dv2 = dv * dv;
#pragma unroll
        for (int t = 0; t < 8; t++) h[t] = fmaf(h[t], dv2, dv * sv[t]);
    }
#pragma unroll
    for (int t = 0; t < 8; t++) {
        int kk = k0 + kh + t;
        As[kh + t][m] = fmaxf(fmaf(h[t], sA[kk], sB[kk]), 0.f);
    }
}

// -------------------- g2small: rows<NN of relu(bn(h1)) @ W2, scaled by dinv ----------
__global__ __launch_bounds__(256) void k_g2small(const float* __restrict__ W2) {
    __shared__ __align__(16) float As[16][128];
    __shared__ __align__(16) float Bs[16][128];
    __shared__ int ssrc[128], sdst[128];
    __shared__ float sdv[128], sA[128], sB[128];
    const int tid = threadIdx.x;
    const int tx = tid & 15, ty = tid >> 4;
    const int row0 = blockIdx.x * 128;
    const int m = tid & 127;
    const int kh = (tid >> 7) * 8;
    const int kb = tid >> 4;
    const int n0 = (tid & 15) * 8;

    if (tid < 128) {
        int rr = row0 + tid;                 // rr < EE always (row0 < NN <= EE-128)
        ssrc[tid] = d_src[rr];
        sdst[tid] = d_dst[rr];
        sdv[tid] = (rr < NN) ? d_dinv[rr] : -1.f;
        sA[tid] = d_bnA[tid];
        sB[tid] = d_bnB[tid];
    }
    __syncthreads();

    float acc[8][8];
#pragma unroll
    for (int i = 0; i < 8; i++)
#pragma unroll
        for (int j = 0; j < 8; j++) acc[i][j] = 0.f;

    for (int k0 = 0; k0 < 128; k0 += 16) {
        build_a_tile(As, ssrc, sdst, sdv, sA, sB, row0, m, kh, k0);
        const float4* bp = reinterpret_cast<const float4*>(
            W2 + (size_t)(k0 + kb) * 128 + n0);
        float4 b0 = bp[0], b1v = bp[1];
        *reinterpret_cast<float4*>(&Bs[kb][n0]) = b0;
        *reinterpret_cast<float4*>(&Bs[kb][n0 + 4]) = b1v;
        __syncthreads();
#pragma unroll
        for (int k = 0; k < 16; k++) {
            float a[8], b[8];
            *reinterpret_cast<float4*>(a)     = *reinterpret_cast<const float4*>(&As[k][ty * 8]);
            *reinterpret_cast<float4*>(a + 4) = *reinterpret_cast<const float4*>(&As[k][ty * 8 + 4]);
            *reinterpret_cast<float4*>(b)     = *reinterpret_cast<const float4*>(&Bs[k][tx * 8]);
            *reinterpret_cast<float4*>(b + 4) = *reinterpret_cast<const float4*>(&Bs[k][tx * 8 + 4]);
#pragma unroll
            for (int i = 0; i < 8; i++)
#pragma unroll
                for (int j = 0; j < 8; j++) acc[i][j] = fmaf(a[i], b[j], acc[i][j]);
        }
        __syncthreads();
    }
#pragma unroll
    for (int i = 0; i < 8; i++) {
        int r = row0 + ty * 8 + i;
        if (r < NN) {
            float dv = d_dinv[r];
            float4 o0 = make_float4(acc[i][0] * dv, acc[i][1] * dv, acc[i][2] * dv, acc[i][3] * dv);
            float4 o1 = make_float4(acc[i][4] * dv, acc[i][5] * dv, acc[i][6] * dv, acc[i][7] * dv);
            float* dst = &d_W0[r * CC + tx * 8];
            reinterpret_cast<float4*>(dst)[0] = o0;
            reinterpret_cast<float4*>(dst)[1] = o1;
        }
    }
}

// -------------------- final fused: GEMM2 + GCN combine + LN + ReLU + W3 dot ----------
__global__ __launch_bounds__(256) void k_final(const float* __restrict__ W2,
                                               const float* __restrict__ b2,
                                               const float* __restrict__ lng,
                                               const float* __restrict__ lnb,
                                               const float* __restrict__ W3,
                                               const float* __restrict__ b3,
                                               float* __restrict__ out) {
    __shared__ __align__(16) float As[16][128];
    __shared__ __align__(16) float Bs[16][128];
    __shared__ int ssrc[128], sdst[128];
    __shared__ float sdv[128], sA[128], sB[128];
    const int tid = threadIdx.x;
    const int tx = tid & 15, ty = tid >> 4;
    const int row0 = blockIdx.x * 128;     // EE = 5000 * 128 exactly
    const int m = tid & 127;
    const int kh = (tid >> 7) * 8;
    const int kb = tid >> 4;
    const int n0 = (tid & 15) * 8;

    if (tid < 128) {
        int rr = row0 + tid;
        ssrc[tid] = d_src[rr];
        sdst[tid] = d_dst[rr];
        sdv[tid] = (rr < NN) ? d_dinv[rr] : -1.f;
        sA[tid] = d_bnA[tid];
        sB[tid] = d_bnB[tid];
    }
    __syncthreads();

    float acc[8][8];
#pragma unroll
    for (int i = 0; i < 8; i++)
#pragma unroll
        for (int j = 0; j < 8; j++) acc[i][j] = 0.f;

    for (int k0 = 0; k0 < 128; k0 += 16) {
        build_a_tile(As, ssrc, sdst, sdv, sA, sB, row0, m, kh, k0);
        const float4* bp = reinterpret_cast<const float4*>(
            W2 + (size_t)(k0 + kb) * 128 + n0);
        float4 b0 = bp[0], b1v = bp[1];
        *reinterpret_cast<float4*>(&Bs[kb][n0]) = b0;
        *reinterpret_cast<float4*>(&Bs[kb][n0 + 4]) = b1v;
        __syncthreads();
#pragma unroll
        for (int k = 0; k < 16; k++) {
            float a[8], b[8];
            *reinterpret_cast<float4*>(a)     = *reinterpret_cast<const float4*>(&As[k][ty * 8]);
            *reinterpret_cast<float4*>(a + 4) = *reinterpret_cast<const float4*>(&As[k][ty * 8 + 4]);
            *reinterpret_cast<float4*>(b)     = *reinterpret_cast<const float4*>(&Bs[k][tx * 8]);
            *reinterpret_cast<float4*>(b + 4) = *reinterpret_cast<const float4*>(&Bs[k][tx * 8 + 4]);
#pragma unroll
            for (int i = 0; i < 8; i++)
#pragma unroll
                for (int j = 0; j < 8; j++) acc[i][j] = fmaf(a[i], b[j], acc[i][j]);
        }
        __syncthreads();
    }

    // per-column constants
    float b2c[8], lgc[8], lbc[8], w3c[8];
#pragma unroll
    for (int j = 0; j < 8; j++) {
        int cj = tx * 8 + j;
        b2c[j] = b2[cj]; lgc[j] = lng[cj]; lbc[j] = lnb[cj]; w3c[j] = W3[cj];
    }
    const float b3v = b3[0];

#pragma unroll
    for (int i = 0; i < 8; i++) {
        int r = row0 + ty * 8 + i;
        float dv = 1.f, d2 = 1.f;
        float s2v[8] = {0, 0, 0, 0, 0, 0, 0, 0};
        if (r < NN) {
            dv = d_dinv[r];
            d2 = dv * dv;
            const float4* sp = reinterpret_cast<const float4*>(&d_S2[r * CC + tx * 8]);
            float4 t0 = sp[0], t1 = sp[1];
            s2v[0] = t0.x; s2v[1] = t0.y; s2v[2] = t0.z; s2v[3] = t0.w;
            s2v[4] = t1.x; s2v[5] = t1.y; s2v[6] = t1.z; s2v[7] = t1.w;
        }
        float val[8], s = 0.f, ss = 0.f;
#pragma unroll
        for (int j = 0; j < 8; j++) {
            float v = fmaf(acc[i][j], d2, fmaf(dv, s2v[j], b2c[j]));
            val[j] = v; s += v; ss += v * v;
        }
#pragma unroll
        for (int o = 8; o; o >>= 1) {
            s  += __shfl_xor_sync(0xffffffffu, s,  o, 16);
            ss += __shfl_xor_sync(0xffffffffu, ss, o, 16);
        }
        float mu = s * (1.f / 128.f);
        float var = ss * (1.f / 128.f) - mu * mu;
        float rstd = rsqrtf(var + EPSV);
        float dot = 0.f;
#pragma unroll
        for (int j = 0; j < 8; j++) {
            float y = fmaf((val[j] - mu) * rstd, lgc[j], lbc[j]);
            y = fmaxf(y, 0.f);
            dot = fmaf(y, w3c[j], dot);
        }
#pragma unroll
        for (int o = 8; o; o >>= 1) dot += __shfl_xor_sync(0xffffffffu, dot, o, 16);
        if (tx == 0) out[r] = dot + b3v;
    }
}

// -------------------- launch --------------------
extern "C" void kernel_launch(void* const* d_in, const int* in_sizes, int n_in,
                              void* d_out, int out_size) {
    const float* x    = (const float*)d_in[0];
    const int*   ei32 = (const int*)d_in[1];      // raw view; dtype resolved on device
    const float* W1   = (const float*)d_in[2];
    const float* b1   = (const float*)d_in[3];
    const float* bn_g = (const float*)d_in[4];
    const float* bn_b = (const float*)d_in[5];
    const float* W2   = (const float*)d_in[6];
    const float* b2   = (const float*)d_in[7];
    const float* ln_g = (const float*)d_in[8];
    const float* ln_b = (const float*)d_in[9];
    const float* W3   = (const float*)d_in[10];
    const float* b3   = (const float*)d_in[11];
    float* out = (float*)d_out;

    k_zero<<<256, 256>>>();
    k_detect<<<1, 32>>>(ei32);
    k_convert<<<1024, 256>>>(ei32);
    k_dinv<<<(NN + 255) / 256, 256>>>();
    k_scan<<<1, 1024>>>();
    k_fill<<<(EE + 255) / 256, 256>>>();
    k_pq<<<dim3((NN + 127) / 128, 2), 256>>>(x, W1);
    k_w0<<<NN, CC>>>();
    k_gather<0><<<NN, CC>>>();
    k_stats<<<EE / 512, CC>>>(b1);
    k_bnfinal<<<1, CC>>>(bn_g, bn_b, b1);
    k_g2small<<<(NN + 127) / 128, 256>>>(W2);
    k_gather<1><<<NN, CC>>>();
    k_final<<<EE / 128, 256>>>(W2, b2, ln_g, ln_b, W3, b3, out);
}

// round 7
// speedup vs baseline: 1.3471x; 1.2370x over previous
#include <cuda_runtime.h>
#include <cuda_bf16.h>
#include <stdint.h>
#include <math.h>

#define NN 20000
#define EE 640000
#define CC 128
#define EPSV 1e-5f
#define ASTRIDE 136

// -------------------- scratch (device globals; no allocation) --------------------
__device__ __align__(16) float  d_PQ[NN * 256];   // [node][0:128]=x@W1_top, [128:256]=x@W1_bot (20MB, L2-resident)
__device__ __align__(16) float  d_W0[NN * CC];
__device__ __align__(16) float  d_S1[NN * CC];
__device__ __align__(16) float  d_S2[NN * CC];
__device__ int    d_src[EE];
__device__ int    d_dst[EE];
__device__ int    d_is64;
__device__ int    d_cnt[NN];
__device__ int    d_start[NN + 1];
__device__ int    d_cursor[NN];
__device__ int    d_srcs[EE];
__device__ float  d_dinv[NN];
__device__ double d_sum[CC];
__device__ double d_sumsq[CC];
__device__ float  d_bnA[CC];
__device__ float  d_bnB[CC];                 // bn offset incl. b1 fold (for raw h)

// -------------------- dtype detect --------------------
__global__ void k_detect(const int* __restrict__ ei32) {
    if (threadIdx.x == 0) {
        int orv = 0;
        for (int i = 0; i < 128; i++) orv |= ei32[2 * i + 1];
        d_is64 = (orv == 0) ? 1 : 0;
    }
}

__global__ void k_zero() {
    int i = blockIdx.x * blockDim.x + threadIdx.x;
    int stride = gridDim.x * blockDim.x;
    for (int j = i; j < NN; j += stride) d_cnt[j] = 0;
    if (i < CC) { d_sum[i] = 0.0; d_sumsq[i] = 0.0; }
}

__global__ void k_convert(const int* __restrict__ ei32) {
    const int is64 = d_is64;
    int i = blockIdx.x * blockDim.x + threadIdx.x;
    int stride = gridDim.x * blockDim.x;
    for (int e = i; e < EE; e += stride) {
        int s, d;
        if (is64) { s = ei32[2 * e]; d = ei32[2 * (EE + e)]; }
        else      { s = ei32[e];     d = ei32[EE + e]; }
        d_src[e] = s;
        d_dst[e] = d;
        atomicAdd(&d_cnt[d], 1);
    }
}

__global__ void k_dinv() {
    int i = blockIdx.x * blockDim.x + threadIdx.x;
    if (i < NN) d_dinv[i] = rsqrtf(1.0f + (float)d_cnt[i]);
}

__global__ void k_scan() {
    __shared__ int sh[1024];
    __shared__ int carry_s;
    const int tid = threadIdx.x;
    if (tid == 0) carry_s = 0;
    __syncthreads();
    for (int base = 0; base < NN; base += 1024) {
        int idx = base + tid;
        int v = (idx < NN) ? d_cnt[idx] : 0;
        sh[tid] = v;
        __syncthreads();
        for (int o = 1; o < 1024; o <<= 1) {
            int t = (tid >= o) ? sh[tid - o] : 0;
            __syncthreads();
            sh[tid] += t;
            __syncthreads();
        }
        int excl = sh[tid] - v + carry_s;
        if (idx < NN) { d_start[idx] = excl; d_cursor[idx] = excl; }
        __syncthreads();
        if (tid == 0) carry_s += sh[1023];
        __syncthreads();
    }
    if (tid == 0) d_start[NN] = carry_s;
}

__global__ void k_fill() {
    int e = blockIdx.x * blockDim.x + threadIdx.x;
    if (e < EE) {
        int d = d_dst[e];
        int pos = atomicAdd(&d_cursor[d], 1);
        d_srcs[pos] = d_src[e];
    }
}

// -------------------- PQ = x @ [W1_top | W1_bot] --------------------
__global__ __launch_bounds__(256) void k_pq(const float* __restrict__ x,
                                            const float* __restrict__ W1) {
    __shared__ __align__(16) float As[16][128];
    __shared__ __align__(16) float Bs[16][128];
    const int tid = threadIdx.x;
    const int tx = tid & 15, ty = tid >> 4;
    const int row0 = blockIdx.x * 128;
    const int half = blockIdx.y;
    const int m = tid & 127;
    const int kh = (tid >> 7) * 8;
    const int kb = tid >> 4;
    const int n0 = (tid & 15) * 8;

    float acc[8][8];
#pragma unroll
    for (int i = 0; i < 8; i++)
#pragma unroll
        for (int j = 0; j < 8; j++) acc[i][j] = 0.f;

    for (int k0 = 0; k0 < 128; k0 += 16) {
        float4 a0 = make_float4(0, 0, 0, 0), a1 = make_float4(0, 0, 0, 0);
        int rr = row0 + m;
        if (rr < NN) {
            const float4* ap = reinterpret_cast<const float4*>(x + (size_t)rr * 128 + k0 + kh);
            a0 = ap[0]; a1 = ap[1];
        }
        As[kh + 0][m] = a0.x; As[kh + 1][m] = a0.y; As[kh + 2][m] = a0.z; As[kh + 3][m] = a0.w;
        As[kh + 4][m] = a1.x; As[kh + 5][m] = a1.y; As[kh + 6][m] = a1.z; As[kh + 7][m] = a1.w;

        const float4* bp = reinterpret_cast<const float4*>(
            W1 + (size_t)(half * 128 + k0 + kb) * 128 + n0);
        float4 b0 = bp[0], b1v = bp[1];
        *reinterpret_cast<float4*>(&Bs[kb][n0]) = b0;
        *reinterpret_cast<float4*>(&Bs[kb][n0 + 4]) = b1v;
        __syncthreads();
#pragma unroll
        for (int k = 0; k < 16; k++) {
            float a[8], b[8];
            *reinterpret_cast<float4*>(a)     = *reinterpret_cast<const float4*>(&As[k][ty * 8]);
            *reinterpret_cast<float4*>(a + 4) = *reinterpret_cast<const float4*>(&As[k][ty * 8 + 4]);
            *reinterpret_cast<float4*>(b)     = *reinterpret_cast<const float4*>(&Bs[k][tx * 8]);
            *reinterpret_cast<float4*>(b + 4) = *reinterpret_cast<const float4*>(&Bs[k][tx * 8 + 4]);
#pragma unroll
            for (int i = 0; i < 8; i++)
#pragma unroll
                for (int j = 0; j < 8; j++) acc[i][j] = fmaf(a[i], b[j], acc[i][j]);
        }
        __syncthreads();
    }
#pragma unroll
    for (int i = 0; i < 8; i++) {
        int r = row0 + ty * 8 + i;
        if (r < NN) {
            float4 o0 = make_float4(acc[i][0], acc[i][1], acc[i][2], acc[i][3]);
            float4 o1 = make_float4(acc[i][4], acc[i][5], acc[i][6], acc[i][7]);
            float* dst = &d_PQ[(size_t)r * 256 + half * 128 + tx * 8];
            reinterpret_cast<float4*>(dst)[0] = o0;
            reinterpret_cast<float4*>(dst)[1] = o1;
        }
    }
}

__global__ void k_w0() {
    int j = blockIdx.x;
    int c = threadIdx.x;
    int s = d_src[j];
    int d = d_dst[j];
    float dv = d_dinv[j];
    d_W0[j * CC + c] = (d_PQ[s * 256 + c] + d_PQ[d * 256 + 128 + c]) * dv;
}

template <int PASS>
__global__ void k_gather() {
    float* S = (PASS == 0) ? d_S1 : d_S2;
    const int d = blockIdx.x;
    const int c = threadIdx.x;
    const int p0 = d_start[d], p1 = d_start[d + 1];
    float a0 = 0.f, a1 = 0.f, a2 = 0.f, a3 = 0.f;
    int p = p0;
    for (; p + 4 <= p1; p += 4) {
        int s0 = d_srcs[p], s1 = d_srcs[p + 1], s2 = d_srcs[p + 2], s3 = d_srcs[p + 3];
        a0 += d_W0[s0 * CC + c];
        a1 += d_W0[s1 * CC + c];
        a2 += d_W0[s2 * CC + c];
        a3 += d_W0[s3 * CC + c];
    }
    for (; p < p1; p++) a0 += d_W0[d_srcs[p] * CC + c];
    S[d * CC + c] = (a0 + a1) + (a2 + a3);
}

__global__ void k_stats(const float* __restrict__ b1) {
    __shared__ int ssrc[512];
    __shared__ int sdst[512];
    const int c = threadIdx.x;
    const int r0 = blockIdx.x * 512;
    for (int i = c; i < 512; i += 128) {
        ssrc[i] = d_src[r0 + i];
        sdst[i] = d_dst[r0 + i];
    }
    __syncthreads();
    const float b1c = b1[c];
    float s = 0.f, ss = 0.f;
#pragma unroll 4
    for (int i = 0; i < 512; i++) {
        int r = r0 + i;
        float h0 = d_PQ[ssrc[i] * 256 + c] + d_PQ[sdst[i] * 256 + 128 + c];
        float h;
        if (r < NN) {
            float dv = d_dinv[r];
            h = fmaf(h0, dv * dv, fmaf(dv, d_S1[r * CC + c], b1c));
        } else {
            h = h0 + b1c;
        }
        s += h; ss += h * h;
    }
    atomicAdd(&d_sum[c], (double)s);
    atomicAdd(&d_sumsq[c], (double)ss);
}

__global__ void k_bnfinal(const float* __restrict__ bn_g, const float* __restrict__ bn_b,
                          const float* __restrict__ b1) {
    int c = threadIdx.x;
    double mu = d_sum[c] / (double)EE;
    double var = d_sumsq[c] / (double)EE - mu * mu;
    float rstd = rsqrtf((float)var + EPSV);
    float a = bn_g[c] * rstd;
    d_bnA[c] = a;
    d_bnB[c] = fmaf(b1[c], a, fmaf(-(float)mu, a, bn_b[c]));
}

// ========== fp32 A-tile builder (for g2small only) ====
__device__ __forceinline__ void build_a_tile(
    float As[16][128], const int* ssrc, const int* sdst, const float* sdv,
    const float* sA, const float* sB, int row0, int m, int kh, int k0) {
    const int s = ssrc[m], d = sdst[m];
    const float dv = sdv[m];
    const float4* pp = reinterpret_cast<const float4*>(&d_PQ[s * 256 + k0 + kh]);
    float4 p0 = pp[0], p1 = pp[1];
    const float4* qp = reinterpret_cast<const float4*>(&d_PQ[d * 256 + 128 + k0 + kh]);
    float4 q0 = qp[0], q1 = qp[1];
    float h[8] = {p0.x + q0.x, p0.y + q0.y, p0.z + q0.z, p0.w + q0.w,
                  p1.x + q1.x, p1.y + q1.y, p1.z + q1.z, p1.w + q1.w};
    if (dv >= 0.f) {
        const float4* s1p = reinterpret_cast<const float4*>(&d_S1[(row0 + m) * CC + k0 + kh]);
        float4 t0 = s1p[0], t1 = s1p[1];
        float sv[8] = {t0.x, t0.y, t0.z, t0.w, t1.x, t1.y, t1.z, t1.w};
        float dv2 = dv * dv;
#pragma unroll
        for (int t = 0; t < 8; t++) h[t] = fmaf(h[t], dv2, dv * sv[t]);
    }
#pragma unroll
    for (int t = 0; t < 8; t++) {
        int kk = k0 + kh + t;
        As[kh + t][m] = fmaxf(fmaf(h[t], sA[kk], sB[kk]), 0.f);
    }
}

// -------------------- g2small (fp32, rows < NN only) --------------------
__global__ __launch_bounds__(256) void k_g2small(const float* __restrict__ W2) {
    __shared__ __align__(16) float As[16][128];
    __shared__ __align__(16) float Bs[16][128];
    __shared__ int ssrc[128], sdst[128];
    __shared__ float sdv[128], sA[128], sB[128];
    const int tid = threadIdx.x;
    const int tx = tid & 15, ty = tid >> 4;
    const int row0 = blockIdx.x * 128;
    const int m = tid & 127;
    const int kh = (tid >> 7) * 8;
    const int kb = tid >> 4;
    const int n0 = (tid & 15) * 8;

    if (tid < 128) {
        int rr = row0 + tid;
        ssrc[tid] = d_src[rr];
        sdst[tid] = d_dst[rr];
        sdv[tid] = (rr < NN) ? d_dinv[rr] : -1.f;
        sA[tid] = d_bnA[tid];
        sB[tid] = d_bnB[tid];
    }
    __syncthreads();

    float acc[8][8];
#pragma unroll
    for (int i = 0; i < 8; i++)
#pragma unroll
        for (int j = 0; j < 8; j++) acc[i][j] = 0.f;

    for (int k0 = 0; k0 < 128; k0 += 16) {
        build_a_tile(As, ssrc, sdst, sdv, sA, sB, row0, m, kh, k0);
        const float4* bp = reinterpret_cast<const float4*>(
            W2 + (size_t)(k0 + kb) * 128 + n0);
        float4 b0 = bp[0], b1v = bp[1];
        *reinterpret_cast<float4*>(&Bs[kb][n0]) = b0;
        *reinterpret_cast<float4*>(&Bs[kb][n0 + 4]) = b1v;
        __syncthreads();
#pragma unroll
        for (int k = 0; k < 16; k++) {
            float a[8], b[8];
            *reinterpret_cast<float4*>(a)     = *reinterpret_cast<const float4*>(&As[k][ty * 8]);
            *reinterpret_cast<float4*>(a + 4) = *reinterpret_cast<const float4*>(&As[k][ty * 8 + 4]);
            *reinterpret_cast<float4*>(b)     = *reinterpret_cast<const float4*>(&Bs[k][tx * 8]);
            *reinterpret_cast<float4*>(b + 4) = *reinterpret_cast<const float4*>(&Bs[k][tx * 8 + 4]);
#pragma unroll
            for (int i = 0; i < 8; i++)
#pragma unroll
                for (int j = 0; j < 8; j++) acc[i][j] = fmaf(a[i], b[j], acc[i][j]);
        }
        __syncthreads();
    }
#pragma unroll
    for (int i = 0; i < 8; i++) {
        int r = row0 + ty * 8 + i;
        if (r < NN) {
            float dv = d_dinv[r];
            float4 o0 = make_float4(acc[i][0] * dv, acc[i][1] * dv, acc[i][2] * dv, acc[i][3] * dv);
            float4 o1 = make_float4(acc[i][4] * dv, acc[i][5] * dv, acc[i][6] * dv, acc[i][7] * dv);
            float* dst = &d_W0[r * CC + tx * 8];
            reinterpret_cast<float4*>(dst)[0] = o0;
            reinterpret_cast<float4*>(dst)[1] = o1;
        }
    }
}

// ==================== k_final: split-bf16 tensor-core GEMM + fused epilogue ============
__device__ __forceinline__ uint32_t su(const void* p) {
    return (uint32_t)__cvta_generic_to_shared(p);
}
__device__ __forceinline__ uint32_t bfbits(__nv_bfloat16 h) {
    return (uint32_t)__bfloat16_as_ushort(h);
}
__device__ __forceinline__ void split2(float v0, float v1, uint32_t& hi, uint32_t& lo) {
    __nv_bfloat16 h0 = __float2bfloat16_rn(v0), h1 = __float2bfloat16_rn(v1);
    float l0f = v0 - __bfloat162float(h0);
    float l1f = v1 - __bfloat162float(h1);
    __nv_bfloat16 l0 = __float2bfloat16_rn(l0f), l1 = __float2bfloat16_rn(l1f);
    hi = (bfbits(h1) << 16) | bfbits(h0);
    lo = (bfbits(l1) << 16) | bfbits(l0);
}

#define LDSM_X4(r0, r1, r2, r3, addr)                                              \
    asm volatile("ldmatrix.sync.aligned.m8n8.x4.shared.b16 {%0,%1,%2,%3},[%4];"    \
                 : "=r"(r0), "=r"(r1), "=r"(r2), "=r"(r3) : "r"(addr))
#define LDSM_X4T(r0, r1, r2, r3, addr)                                                  \
    asm volatile("ldmatrix.sync.aligned.m8n8.x4.trans.shared.b16 {%0,%1,%2,%3},[%4];"   \
                 : "=r"(r0), "=r"(r1), "=r"(r2), "=r"(r3) : "r"(addr))
#define MMA16816(d, a0, a1, a2, a3, b0, b1)                                             \
    asm volatile("mma.sync.aligned.m16n8k16.row.col.f32.bf16.bf16.f32 "                 \
                 "{%0,%1,%2,%3},{%4,%5,%6,%7},{%8,%9},{%0,%1,%2,%3};"                   \
                 : "+f"(d[0]), "+f"(d[1]), "+f"(d[2]), "+f"(d[3])                       \
                 : "r"(a0), "r"(a1), "r"(a2), "r"(a3), "r"(b0), "r"(b1))

__global__ __launch_bounds__(256) void k_final(const float* __restrict__ W2,
                                               const float* __restrict__ b2,
                                               const float* __restrict__ lng,
                                               const float* __restrict__ lnb,
                                               const float* __restrict__ W3,
                                               const float* __restrict__ b3,
                                               float* __restrict__ out) {
    extern __shared__ __align__(16) char dynsmem[];
    __nv_bfloat16* Ah = (__nv_bfloat16*)dynsmem;          // [128][ASTRIDE]
    __nv_bfloat16* Al = Ah + 128 * ASTRIDE;
    __nv_bfloat16* Bh = Al + 128 * ASTRIDE;               // [128 k][ASTRIDE n]
    __nv_bfloat16* Bl = Bh + 128 * ASTRIDE;

    __shared__ float sA[128], sB[128], sb2[128], slg[128], slb[128], sw3[128];

    const int tid = threadIdx.x;
    const int lane = tid & 31;
    const int w = tid >> 5;
    const int row0 = blockIdx.x * 128;

    if (tid < 128) {
        sA[tid] = d_bnA[tid];
        sB[tid] = d_bnB[tid];
        sb2[tid] = b2[tid];
        slg[tid] = lng[tid];
        slb[tid] = lnb[tid];
        sw3[tid] = W3[tid];
    }
    __syncthreads();

    // ---- build A tiles: row = tid/2 (edge), k-half = (tid&1)*64 ----
    {
        const int arow = tid >> 1;
        const int kh = (tid & 1) * 64;
        const int r = row0 + arow;
        const int s = d_src[r], d = d_dst[r];
        const float dv = (r < NN) ? d_dinv[r] : -1.f;
        const float dv2 = dv * dv;
        const float4* pp = reinterpret_cast<const float4*>(&d_PQ[s * 256 + kh]);
        const float4* qp = reinterpret_cast<const float4*>(&d_PQ[d * 256 + 128 + kh]);
        const float4* s1p = reinterpret_cast<const float4*>(&d_S1[r * CC + kh]);
        uint32_t* ahp = reinterpret_cast<uint32_t*>(&Ah[arow * ASTRIDE + kh]);
        uint32_t* alp = reinterpret_cast<uint32_t*>(&Al[arow * ASTRIDE + kh]);
#pragma unroll 4
        for (int i = 0; i < 16; i++) {
            float4 p = pp[i], q = qp[i];
            float h0 = p.x + q.x, h1 = p.y + q.y, h2 = p.z + q.z, h3 = p.w + q.w;
            if (dv >= 0.f) {
                float4 t = s1p[i];
                h0 = fmaf(h0, dv2, dv * t.x);
                h1 = fmaf(h1, dv2, dv * t.y);
                h2 = fmaf(h2, dv2, dv * t.z);
                h3 = fmaf(h3, dv2, dv * t.w);
            }
            int c = kh + 4 * i;
            float v0 = fmaxf(fmaf(h0, sA[c + 0], sB[c + 0]), 0.f);
            float v1 = fmaxf(fmaf(h1, sA[c + 1], sB[c + 1]), 0.f);
            float v2 = fmaxf(fmaf(h2, sA[c + 2], sB[c + 2]), 0.f);
            float v3 = fmaxf(fmaf(h3, sA[c + 3], sB[c + 3]), 0.f);
            uint32_t hi0, lo0, hi1, lo1;
            split2(v0, v1, hi0, lo0);
            split2(v2, v3, hi1, lo1);
            ahp[2 * i] = hi0; ahp[2 * i + 1] = hi1;
            alp[2 * i] = lo0; alp[2 * i + 1] = lo1;
        }
    }
    // ---- build B tiles: k-row = tid/2, n-half = (tid&1)*64 ----
    {
        const int krow = tid >> 1;
        const int nh = (tid & 1) * 64;
        const float4* wp = reinterpret_cast<const float4*>(&W2[(size_t)krow * 128 + nh]);
        uint32_t* bhp = reinterpret_cast<uint32_t*>(&Bh[krow * ASTRIDE + nh]);
        uint32_t* blp = reinterpret_cast<uint32_t*>(&Bl[krow * ASTRIDE + nh]);
#pragma unroll 4
        for (int i = 0; i < 16; i++) {
            float4 v = wp[i];
            uint32_t hi0, lo0, hi1, lo1;
            split2(v.x, v.y, hi0, lo0);
            split2(v.z, v.w, hi1, lo1);
            bhp[2 * i] = hi0; bhp[2 * i + 1] = hi1;
            blp[2 * i] = lo0; blp[2 * i + 1] = lo1;
        }
    }
    __syncthreads();

    // ---- mma mainloop: warp w owns rows 16w..16w+15, all 128 cols ----
    float acc[16][4];
#pragma unroll
    for (int i = 0; i < 16; i++)
#pragma unroll
        for (int j = 0; j < 4; j++) acc[i][j] = 0.f;

    const int aRowOff = (w * 16 + (lane & 15)) * ASTRIDE + ((lane >> 4) << 3);
    const uint32_t aHB = su(Ah), aLB = su(Al);
    const int bRowK = (lane & 7) + (((lane >> 3) & 1) << 3);
    const int bColN = (lane >> 4) << 3;
    const uint32_t bHB = su(Bh), bLB = su(Bl);

    for (int k0 = 0; k0 < 128; k0 += 16) {
        uint32_t ah0, ah1, ah2, ah3, al0, al1, al2, al3;
        LDSM_X4(ah0, ah1, ah2, ah3, aHB + 2u * (aRowOff + k0));
        LDSM_X4(al0, al1, al2, al3, aLB + 2u * (aRowOff + k0));
        const int bKOff = (bRowK + k0) * ASTRIDE + bColN;
#pragma unroll
        for (int nt2 = 0; nt2 < 8; nt2++) {
            const int n0 = nt2 * 16;
            uint32_t bh0, bh1, bh2, bh3, bl0, bl1, bl2, bl3;
            LDSM_X4T(bh0, bh1, bh2, bh3, bHB + 2u * (bKOff + n0));
            LDSM_X4T(bl0, bl1, bl2, bl3, bLB + 2u * (bKOff + n0));
            MMA16816(acc[2 * nt2],     ah0, ah1, ah2, ah3, bh0, bh1);
            MMA16816(acc[2 * nt2],     ah0, ah1, ah2, ah3, bl0, bl1);
            MMA16816(acc[2 * nt2],     al0, al1, al2, al3, bh0, bh1);
            MMA16816(acc[2 * nt2 + 1], ah0, ah1, ah2, ah3, bh2, bh3);
            MMA16816(acc[2 * nt2 + 1], ah0, ah1, ah2, ah3, bl2, bl3);
            MMA16816(acc[2 * nt2 + 1], al0, al1, al2, al3, bh2, bh3);
        }
    }

    // ---- epilogue: GCN combine + LN + ReLU + W3 dot ----
    const int r0 = row0 + w * 16 + (lane >> 2);
    const int r1 = r0 + 8;
    float dv0 = 1.f, d20 = 1.f, dv1 = 1.f, d21 = 1.f;
    if (r0 < NN) { dv0 = d_dinv[r0]; d20 = dv0 * dv0; }
    if (r1 < NN) { dv1 = d_dinv[r1]; d21 = dv1 * dv1; }
    const int cbase = (lane & 3) * 2;

    float s0 = 0.f, ss0 = 0.f, s1 = 0.f, ss1 = 0.f;
#pragma unroll
    for (int nt = 0; nt < 16; nt++) {
        const int c = nt * 8 + cbase;
        float2 sv0 = make_float2(0.f, 0.f), sv1 = make_float2(0.f, 0.f);
        if (r0 < NN) sv0 = *reinterpret_cast<const float2*>(&d_S2[r0 * CC + c]);
        if (r1 < NN) sv1 = *reinterpret_cast<const float2*>(&d_S2[r1 * CC + c]);
        float v00 = fmaf(acc[nt][0], d20, fmaf(dv0, sv0.x, sb2[c]));
        float v01 = fmaf(acc[nt][1], d20, fmaf(dv0, sv0.y, sb2[c + 1]));
        float v10 = fmaf(acc[nt][2], d21, fmaf(dv1, sv1.x, sb2[c]));
        float v11 = fmaf(acc[nt][3], d21, fmaf(dv1, sv1.y, sb2[c + 1]));
        acc[nt][0] = v00; acc[nt][1] = v01; acc[nt][2] = v10; acc[nt][3] = v11;
        s0 += v00 + v01; ss0 += v00 * v00 + v01 * v01;
        s1 += v10 + v11; ss1 += v10 * v10 + v11 * v11;
    }
#pragma unroll
    for (int o = 1; o <= 2; o <<= 1) {
        s0  += __shfl_xor_sync(0xffffffffu, s0,  o);
        ss0 += __shfl_xor_sync(0xffffffffu, ss0, o);
        s1  += __shfl_xor_sync(0xffffffffu, s1,  o);
        ss1 += __shfl_xor_sync(0xffffffffu, ss1, o);
    }
    const float inv = 1.f / 128.f;
    float mu0 = s0 * inv, mu1 = s1 * inv;
    float rstd0 = rsqrtf(ss0 * inv - mu0 * mu0 + EPSV);
    float rstd1 = rsqrtf(ss1 * inv - mu1 * mu1 + EPSV);
    float dot0 = 0.f, dot1 = 0.f;
#pragma unroll
    for (int nt = 0; nt < 16; nt++) {
        const int c = nt * 8 + cbase;
        float y;
        y = fmaf((acc[nt][0] - mu0) * rstd0, slg[c],     slb[c]);     dot0 = fmaf(fmaxf(y, 0.f), sw3[c],     dot0);
        y = fmaf((acc[nt][1] - mu0) * rstd0, slg[c + 1], slb[c + 1]); dot0 = fmaf(fmaxf(y, 0.f), sw3[c + 1], dot0);
        y = fmaf((acc[nt][2] - mu1) * rstd1, slg[c],     slb[c]);     dot1 = fmaf(fmaxf(y, 0.f), sw3[c],     dot1);
        y = fmaf((acc[nt][3] - mu1) * rstd1, slg[c + 1], slb[c + 1]); dot1 = fmaf(fmaxf(y, 0.f), sw3[c + 1], dot1);
    }
#pragma unroll
    for (int o = 1; o <= 2; o <<= 1) {
        dot0 += __shfl_xor_sync(0xffffffffu, dot0, o);
        dot1 += __shfl_xor_sync(0xffffffffu, dot1, o);
    }
    if ((lane & 3) == 0) {
        const float b3v = b3[0];
        out[r0] = dot0 + b3v;
        out[r1] = dot1 + b3v;
    }
}

// -------------------- launch --------------------
extern "C" void kernel_launch(void* const* d_in, const int* in_sizes, int n_in,
                              void* d_out, int out_size) {
    const float* x    = (const float*)d_in[0];
    const int*   ei32 = (const int*)d_in[1];
    const float* W1   = (const float*)d_in[2];
    const float* b1   = (const float*)d_in[3];
    const float* bn_g = (const float*)d_in[4];
    const float* bn_b = (const float*)d_in[5];
    const float* W2   = (const float*)d_in[6];
    const float* b2   = (const float*)d_in[7];
    const float* ln_g = (const float*)d_in[8];
    const float* ln_b = (const float*)d_in[9];
    const float* W3   = (const float*)d_in[10];
    const float* b3   = (const float*)d_in[11];
    float* out = (float*)d_out;

    const int FIN_SMEM = 4 * 128 * ASTRIDE * 2;   // 139,264 B
    cudaFuncSetAttribute(k_final, cudaFuncAttributeMaxDynamicSharedMemorySize, FIN_SMEM);

    k_zero<<<256, 256>>>();
    k_detect<<<1, 32>>>(ei32);
    k_convert<<<1024, 256>>>(ei32);
    k_dinv<<<(NN + 255) / 256, 256>>>();
    k_scan<<<1, 1024>>>();
    k_fill<<<(EE + 255) / 256, 256>>>();
    k_pq<<<dim3((NN + 127) / 128, 2), 256>>>(x, W1);
    k_w0<<<NN, CC>>>();
    k_gather<0><<<NN, CC>>>();
    k_stats<<<EE / 512, CC>>>(b1);
    k_bnfinal<<<1, CC>>>(bn_g, bn_b, b1);
    k_g2small<<<(NN + 127) / 128, 256>>>(W2);
    k_gather<1><<<NN, CC>>>();
    k_final<<<EE / 128, 256, FIN_SMEM>>>(W2, b2, ln_g, ln_b, W3, b3, out);
}

// round 9
// speedup vs baseline: 1.3867x; 1.0294x over previous
#include <cuda_runtime.h>
#include <cuda_bf16.h>
#include <stdint.h>
#include <math.h>

#define NN 20000
#define EE 640000
#define CC 128
#define EPSV 1e-5f
#define ASTRIDE 136

// -------------------- scratch (device globals; no allocation) --------------------
__device__ __align__(16) float  d_PQ[NN * 256];   // [node][0:128]=P, [128:256]=Q (20MB, L2-resident)
__device__ __align__(16) float  d_W0[NN * CC];
__device__ __align__(16) float  d_S1[NN * CC];
__device__ __align__(16) float  d_S2[NN * CC];
__device__ __align__(16) __nv_bfloat16 d_Bh[128 * ASTRIDE];  // W2 hi, padded rows
__device__ __align__(16) __nv_bfloat16 d_Bl[128 * ASTRIDE];  // W2 lo
__device__ int    d_src[EE];
__device__ int    d_dst[EE];
__device__ int    d_is64;
__device__ int    d_cnt[NN];
__device__ int    d_start[NN + 1];
__device__ int    d_cursor[NN];
__device__ int    d_srcs[EE];
__device__ float  d_dinv[NN];
__device__ double d_sum[CC];
__device__ double d_sumsq[CC];
__device__ float  d_bnA[CC];
__device__ float  d_bnB[CC];

// -------------------- dtype detect --------------------
__global__ void k_detect(const int* __restrict__ ei32) {
    if (threadIdx.x == 0) {
        int orv = 0;
        for (int i = 0; i < 128; i++) orv |= ei32[2 * i + 1];
        d_is64 = (orv == 0) ? 1 : 0;
    }
}

__global__ void k_zero() {
    int i = blockIdx.x * blockDim.x + threadIdx.x;
    int stride = gridDim.x * blockDim.x;
    for (int j = i; j < NN; j += stride) d_cnt[j] = 0;
    if (i < CC) { d_sum[i] = 0.0; d_sumsq[i] = 0.0; }
}

__global__ void k_convert(const int* __restrict__ ei32) {
    const int is64 = d_is64;
    int i = blockIdx.x * blockDim.x + threadIdx.x;
    int stride = gridDim.x * blockDim.x;
    for (int e = i; e < EE; e += stride) {
        int s, d;
        if (is64) { s = ei32[2 * e]; d = ei32[2 * (EE + e)]; }
        else      { s = ei32[e];     d = ei32[EE + e]; }
        d_src[e] = s;
        d_dst[e] = d;
        atomicAdd(&d_cnt[d], 1);
    }
}

__global__ void k_dinv() {
    int i = blockIdx.x * blockDim.x + threadIdx.x;
    if (i < NN) d_dinv[i] = rsqrtf(1.0f + (float)d_cnt[i]);
}

__global__ void k_scan() {
    __shared__ int sh[1024];
    __shared__ int carry_s;
    const int tid = threadIdx.x;
    if (tid == 0) carry_s = 0;
    __syncthreads();
    for (int base = 0; base < NN; base += 1024) {
        int idx = base + tid;
        int v = (idx < NN) ? d_cnt[idx] : 0;
        sh[tid] = v;
        __syncthreads();
        for (int o = 1; o < 1024; o <<= 1) {
            int t = (tid >= o) ? sh[tid - o] : 0;
            __syncthreads();
            sh[tid] += t;
            __syncthreads();
        }
        int excl = sh[tid] - v + carry_s;
        if (idx < NN) { d_start[idx] = excl; d_cursor[idx] = excl; }
        __syncthreads();
        if (tid == 0) carry_s += sh[1023];
        __syncthreads();
    }
    if (tid == 0) d_start[NN] = carry_s;
}

__global__ void k_fill() {
    int e = blockIdx.x * blockDim.x + threadIdx.x;
    if (e < EE) {
        int d = d_dst[e];
        int pos = atomicAdd(&d_cursor[d], 1);
        d_srcs[pos] = d_src[e];
    }
}

// -------------------- W2 pre-split into padded hi/lo bf16 --------------------
__global__ void k_prepw(const float* __restrict__ W2) {
    int idx = blockIdx.x * blockDim.x + threadIdx.x;   // 16384
    int k = idx >> 7, n = idx & 127;
    float v = W2[(size_t)k * 128 + n];
    __nv_bfloat16 h = __float2bfloat16_rn(v);
    __nv_bfloat16 l = __float2bfloat16_rn(v - __bfloat162float(h));
    d_Bh[k * ASTRIDE + n] = h;
    d_Bl[k * ASTRIDE + n] = l;
}

// -------------------- PQ = x @ [W1_top | W1_bot] --------------------
__global__ __launch_bounds__(256) void k_pq(const float* __restrict__ x,
                                            const float* __restrict__ W1) {
    __shared__ __align__(16) float As[16][128];
    __shared__ __align__(16) float Bs[16][128];
    const int tid = threadIdx.x;
    const int tx = tid & 15, ty = tid >> 4;
    const int row0 = blockIdx.x * 128;
    const int half = blockIdx.y;
    const int m = tid & 127;
    const int kh = (tid >> 7) * 8;
    const int kb = tid >> 4;
    const int n0 = (tid & 15) * 8;

    float acc[8][8];
#pragma unroll
    for (int i = 0; i < 8; i++)
#pragma unroll
        for (int j = 0; j < 8; j++) acc[i][j] = 0.f;

    for (int k0 = 0; k0 < 128; k0 += 16) {
        float4 a0 = make_float4(0, 0, 0, 0), a1 = make_float4(0, 0, 0, 0);
        int rr = row0 + m;
        if (rr < NN) {
            const float4* ap = reinterpret_cast<const float4*>(x + (size_t)rr * 128 + k0 + kh);
            a0 = ap[0]; a1 = ap[1];
        }
        As[kh + 0][m] = a0.x; As[kh + 1][m] = a0.y; As[kh + 2][m] = a0.z; As[kh + 3][m] = a0.w;
        As[kh + 4][m] = a1.x; As[kh + 5][m] = a1.y; As[kh + 6][m] = a1.z; As[kh + 7][m] = a1.w;

        const float4* bp = reinterpret_cast<const float4*>(
            W1 + (size_t)(half * 128 + k0 + kb) * 128 + n0);
        float4 b0 = bp[0], b1v = bp[1];
        *reinterpret_cast<float4*>(&Bs[kb][n0]) = b0;
        *reinterpret_cast<float4*>(&Bs[kb][n0 + 4]) = b1v;
        __syncthreads();
#pragma unroll
        for (int k = 0; k < 16; k++) {
            float a[8], b[8];
            *reinterpret_cast<float4*>(a)     = *reinterpret_cast<const float4*>(&As[k][ty * 8]);
            *reinterpret_cast<float4*>(a + 4) = *reinterpret_cast<const float4*>(&As[k][ty * 8 + 4]);
            *reinterpret_cast<float4*>(b)     = *reinterpret_cast<const float4*>(&Bs[k][tx * 8]);
            *reinterpret_cast<float4*>(b + 4) = *reinterpret_cast<const float4*>(&Bs[k][tx * 8 + 4]);
#pragma unroll
            for (int i = 0; i < 8; i++)
#pragma unroll
                for (int j = 0; j < 8; j++) acc[i][j] = fmaf(a[i], b[j], acc[i][j]);
        }
        __syncthreads();
    }
#pragma unroll
    for (int i = 0; i < 8; i++) {
        int r = row0 + ty * 8 + i;
        if (r < NN) {
            float4 o0 = make_float4(acc[i][0], acc[i][1], acc[i][2], acc[i][3]);
            float4 o1 = make_float4(acc[i][4], acc[i][5], acc[i][6], acc[i][7]);
            float* dst = &d_PQ[(size_t)r * 256 + half * 128 + tx * 8];
            reinterpret_cast<float4*>(dst)[0] = o0;
            reinterpret_cast<float4*>(dst)[1] = o1;
        }
    }
}

__global__ void k_w0() {
    int j = blockIdx.x;
    int c = threadIdx.x;
    int s = d_src[j];
    int d = d_dst[j];
    float dv = d_dinv[j];
    d_W0[j * CC + c] = (d_PQ[s * 256 + c] + d_PQ[d * 256 + 128 + c]) * dv;
}

template <int PASS>
__global__ void k_gather() {
    float* S = (PASS == 0) ? d_S1 : d_S2;
    const int d = blockIdx.x;
    const int c = threadIdx.x;
    const int p0 = d_start[d], p1 = d_start[d + 1];
    float a0 = 0.f, a1 = 0.f, a2 = 0.f, a3 = 0.f;
    int p = p0;
    for (; p + 4 <= p1; p += 4) {
        int s0 = d_srcs[p], s1 = d_srcs[p + 1], s2 = d_srcs[p + 2], s3 = d_srcs[p + 3];
        a0 += d_W0[s0 * CC + c];
        a1 += d_W0[s1 * CC + c];
        a2 += d_W0[s2 * CC + c];
        a3 += d_W0[s3 * CC + c];
    }
    for (; p < p1; p++) a0 += d_W0[d_srcs[p] * CC + c];
    S[d * CC + c] = (a0 + a1) + (a2 + a3);
}

__global__ void k_stats(const float* __restrict__ b1) {
    __shared__ int ssrc[512];
    __shared__ int sdst[512];
    const int c = threadIdx.x;
    const int r0 = blockIdx.x * 512;
    for (int i = c; i < 512; i += 128) {
        ssrc[i] = d_src[r0 + i];
        sdst[i] = d_dst[r0 + i];
    }
    __syncthreads();
    const float b1c = b1[c];
    float s = 0.f, ss = 0.f;
#pragma unroll 4
    for (int i = 0; i < 512; i++) {
        int r = r0 + i;
        float h0 = d_PQ[ssrc[i] * 256 + c] + d_PQ[sdst[i] * 256 + 128 + c];
        float h;
        if (r < NN) {
            float dv = d_dinv[r];
            h = fmaf(h0, dv * dv, fmaf(dv, d_S1[r * CC + c], b1c));
        } else {
            h = h0 + b1c;
        }
        s += h; ss += h * h;
    }
    atomicAdd(&d_sum[c], (double)s);
    atomicAdd(&d_sumsq[c], (double)ss);
}

__global__ void k_bnfinal(const float* __restrict__ bn_g, const float* __restrict__ bn_b,
                          const float* __restrict__ b1) {
    int c = threadIdx.x;
    double mu = d_sum[c] / (double)EE;
    double var = d_sumsq[c] / (double)EE - mu * mu;
    float rstd = rsqrtf((float)var + EPSV);
    float a = bn_g[c] * rstd;
    d_bnA[c] = a;
    d_bnB[c] = fmaf(b1[c], a, fmaf(-(float)mu, a, bn_b[c]));
}

// ========== fp32 A-tile builder (for g2small only) ====
__device__ __forceinline__ void build_a_tile(
    float As[16][128], const int* ssrc, const int* sdst, const float* sdv,
    const float* sA, const float* sB, int row0, int m, int kh, int k0) {
    const int s = ssrc[m], d = sdst[m];
    const float dv = sdv[m];
    const float4* pp = reinterpret_cast<const float4*>(&d_PQ[s * 256 + k0 + kh]);
    float4 p0 = pp[0], p1 = pp[1];
    const float4* qp = reinterpret_cast<const float4*>(&d_PQ[d * 256 + 128 + k0 + kh]);
    float4 q0 = qp[0], q1 = qp[1];
    float h[8] = {p0.x + q0.x, p0.y + q0.y, p0.z + q0.z, p0.w + q0.w,
                  p1.x + q1.x, p1.y + q1.y, p1.z + q1.z, p1.w + q1.w};
    if (dv >= 0.f) {
        const float4* s1p = reinterpret_cast<const float4*>(&d_S1[(row0 + m) * CC + k0 + kh]);
        float4 t0 = s1p[0], t1 = s1p[1];
        float sv[8] = {t0.x, t0.y, t0.z, t0.w, t1.x, t1.y, t1.z, t1.w};
        float dv2 = dv * dv;
#pragma unroll
        for (int t = 0; t < 8; t++) h[t] = fmaf(h[t], dv2, dv * sv[t]);
    }
#pragma unroll
    for (int t = 0; t < 8; t++) {
        int kk = k0 + kh + t;
        As[kh + t][m] = fmaxf(fmaf(h[t], sA[kk], sB[kk]), 0.f);
    }
}

// -------------------- g2small (fp32, rows < NN only) --------------------
__global__ __launch_bounds__(256) void k_g2small(const float* __restrict__ W2) {
    __shared__ __align__(16) float As[16][128];
    __shared__ __align__(16) float Bs[16][128];
    __shared__ int ssrc[128], sdst[128];
    __shared__ float sdv[128], sA[128], sB[128];
    const int tid = threadIdx.x;
    const int tx = tid & 15, ty = tid >> 4;
    const int row0 = blockIdx.x * 128;
    const int m = tid & 127;
    const int kh = (tid >> 7) * 8;
    const int kb = tid >> 4;
    const int n0 = (tid & 15) * 8;

    if (tid < 128) {
        int rr = row0 + tid;
        ssrc[tid] = d_src[rr];
        sdst[tid] = d_dst[rr];
        sdv[tid] = (rr < NN) ? d_dinv[rr] : -1.f;
        sA[tid] = d_bnA[tid];
        sB[tid] = d_bnB[tid];
    }
    __syncthreads();

    float acc[8][8];
#pragma unroll
    for (int i = 0; i < 8; i++)
#pragma unroll
        for (int j = 0; j < 8; j++) acc[i][j] = 0.f;

    for (int k0 = 0; k0 < 128; k0 += 16) {
        build_a_tile(As, ssrc, sdst, sdv, sA, sB, row0, m, kh, k0);
        const float4* bp = reinterpret_cast<const float4*>(
            W2 + (size_t)(k0 + kb) * 128 + n0);
        float4 b0 = bp[0], b1v = bp[1];
        *reinterpret_cast<float4*>(&Bs[kb][n0]) = b0;
        *reinterpret_cast<float4*>(&Bs[kb][n0 + 4]) = b1v;
        __syncthreads();
#pragma unroll
        for (int k = 0; k < 16; k++) {
            float a[8], b[8];
            *reinterpret_cast<float4*>(a)     = *reinterpret_cast<const float4*>(&As[k][ty * 8]);
            *reinterpret_cast<float4*>(a + 4) = *reinterpret_cast<const float4*>(&As[k][ty * 8 + 4]);
            *reinterpret_cast<float4*>(b)     = *reinterpret_cast<const float4*>(&Bs[k][tx * 8]);
            *reinterpret_cast<float4*>(b + 4) = *reinterpret_cast<const float4*>(&Bs[k][tx * 8 + 4]);
#pragma unroll
            for (int i = 0; i < 8; i++)
#pragma unroll
                for (int j = 0; j < 8; j++) acc[i][j] = fmaf(a[i], b[j], acc[i][j]);
        }
        __syncthreads();
    }
#pragma unroll
    for (int i = 0; i < 8; i++) {
        int r = row0 + ty * 8 + i;
        if (r < NN) {
            float dv = d_dinv[r];
            float4 o0 = make_float4(acc[i][0] * dv, acc[i][1] * dv, acc[i][2] * dv, acc[i][3] * dv);
            float4 o1 = make_float4(acc[i][4] * dv, acc[i][5] * dv, acc[i][6] * dv, acc[i][7] * dv);
            float* dst = &d_W0[r * CC + tx * 8];
            reinterpret_cast<float4*>(dst)[0] = o0;
            reinterpret_cast<float4*>(dst)[1] = o1;
        }
    }
}

// ==================== k_final: split-bf16 mma.sync + fused epilogue ====================
__device__ __forceinline__ uint32_t su(const void* p) {
    return (uint32_t)__cvta_generic_to_shared(p);
}
__device__ __forceinline__ void split2(float v0, float v1, uint32_t& hi, uint32_t& lo) {
    __nv_bfloat16 h0 = __float2bfloat16_rn(v0), h1 = __float2bfloat16_rn(v1);
    float l0f = v0 - __bfloat162float(h0);
    float l1f = v1 - __bfloat162float(h1);
    __nv_bfloat16 l0 = __float2bfloat16_rn(l0f), l1 = __float2bfloat16_rn(l1f);
    hi = ((uint32_t)__bfloat16_as_ushort(h1) << 16) | (uint32_t)__bfloat16_as_ushort(h0);
    lo = ((uint32_t)__bfloat16_as_ushort(l1) << 16) | (uint32_t)__bfloat16_as_ushort(l0);
}

#define LDSM_X4(r0, r1, r2, r3, addr)                                              \
    asm volatile("ldmatrix.sync.aligned.m8n8.x4.shared.b16 {%0,%1,%2,%3},[%4];"    \
                 : "=r"(r0), "=r"(r1), "=r"(r2), "=r"(r3) : "r"(addr))
#define LDSM_X4T(r0, r1, r2, r3, addr)                                                  \
    asm volatile("ldmatrix.sync.aligned.m8n8.x4.trans.shared.b16 {%0,%1,%2,%3},[%4];"   \
                 : "=r"(r0), "=r"(r1), "=r"(r2), "=r"(r3) : "r"(addr))
#define MMA16816(d, a0, a1, a2, a3, b0, b1)                                             \
    asm volatile("mma.sync.aligned.m16n8k16.row.col.f32.bf16.bf16.f32 "                 \
                 "{%0,%1,%2,%3},{%4,%5,%6,%7},{%8,%9},{%0,%1,%2,%3};"                   \
                 : "+f"(d[0]), "+f"(d[1]), "+f"(d[2]), "+f"(d[3])                       \
                 : "r"(a0), "r"(a1), "r"(a2), "r"(a3), "r"(b0), "r"(b1))

__global__ __launch_bounds__(256) void k_final(const float* __restrict__ b2,
                                               const float* __restrict__ lng,
                                               const float* __restrict__ lnb,
                                               const float* __restrict__ W3,
                                               const float* __restrict__ b3,
                                               float* __restrict__ out) {
    extern __shared__ __align__(16) char dynsmem[];
    __nv_bfloat16* Ah = (__nv_bfloat16*)dynsmem;          // [128][ASTRIDE]
    __nv_bfloat16* Al = Ah + 128 * ASTRIDE;
    __nv_bfloat16* Bh = Al + 128 * ASTRIDE;               // [128 k][ASTRIDE n]
    __nv_bfloat16* Bl = Bh + 128 * ASTRIDE;

    __shared__ float sA[128], sB[128], sb2[128], slg[128], slb[128], sw3[128];
    __shared__ float redS[2][128], redSS[2][128], redD[2][128];

    const int tid = threadIdx.x;
    const int lane = tid & 31;
    const int w = tid >> 5;
    const int row0 = blockIdx.x * 128;

    if (tid < 128) {
        sA[tid] = d_bnA[tid];
        sB[tid] = d_bnB[tid];
        sb2[tid] = b2[tid];
        slg[tid] = lng[tid];
        slb[tid] = lnb[tid];
        sw3[tid] = W3[tid];
    }

    // ---- copy pre-split, padded B (2 x 34,816 B) ----
    {
        const uint4* gh = reinterpret_cast<const uint4*>(d_Bh);
        const uint4* gl = reinterpret_cast<const uint4*>(d_Bl);
        uint4* sh = reinterpret_cast<uint4*>(Bh);
        uint4* sl = reinterpret_cast<uint4*>(Bl);
        for (int i = tid; i < 2176; i += 256) {
            sh[i] = gh[i];
            sl[i] = gl[i];
        }
    }

    // ---- build A tiles: row = tid/2 (edge), k-half = (tid&1)*64 ----
    {
        const int arow = tid >> 1;
        const int kh = (tid & 1) * 64;
        const int r = row0 + arow;
        const int s = d_src[r], d = d_dst[r];
        const float dv = (r < NN) ? d_dinv[r] : -1.f;
        const float dv2 = dv * dv;
        const float4* pp = reinterpret_cast<const float4*>(&d_PQ[s * 256 + kh]);
        const float4* qp = reinterpret_cast<const float4*>(&d_PQ[d * 256 + 128 + kh]);
        const float4* s1p = reinterpret_cast<const float4*>(&d_S1[r * CC + kh]);
        __syncthreads();   // sA/sB visible
        uint32_t* ahp = reinterpret_cast<uint32_t*>(&Ah[arow * ASTRIDE + kh]);
        uint32_t* alp = reinterpret_cast<uint32_t*>(&Al[arow * ASTRIDE + kh]);
#pragma unroll 4
        for (int i = 0; i < 16; i++) {
            float4 p = pp[i], q = qp[i];
            float h0 = p.x + q.x, h1 = p.y + q.y, h2 = p.z + q.z, h3 = p.w + q.w;
            if (dv >= 0.f) {
                float4 t = s1p[i];
                h0 = fmaf(h0, dv2, dv * t.x);
                h1 = fmaf(h1, dv2, dv * t.y);
                h2 = fmaf(h2, dv2, dv * t.z);
                h3 = fmaf(h3, dv2, dv * t.w);
            }
            int c = kh + 4 * i;
            float v0 = fmaxf(fmaf(h0, sA[c + 0], sB[c + 0]), 0.f);
            float v1 = fmaxf(fmaf(h1, sA[c + 1], sB[c + 1]), 0.f);
            float v2 = fmaxf(fmaf(h2, sA[c + 2], sB[c + 2]), 0.f);
            float v3 = fmaxf(fmaf(h3, sA[c + 3], sB[c + 3]), 0.f);
            uint32_t hi0, lo0, hi1, lo1;
            split2(v0, v1, hi0, lo0);
            split2(v2, v3, hi1, lo1);
            ahp[2 * i] = hi0; ahp[2 * i + 1] = hi1;
            alp[2 * i] = lo0; alp[2 * i + 1] = lo1;
        }
    }
    __syncthreads();

    // ---- mma mainloop: warp (rowgrp = w&3, half = w>>2): rows rowgrp*32..+31, cols half*64..+63
    const int rowgrp = w & 3;
    const int half = w >> 2;

    float acc0[8][4], acc1[8][4];
#pragma unroll
    for (int i = 0; i < 8; i++)
#pragma unroll
        for (int j = 0; j < 4; j++) { acc0[i][j] = 0.f; acc1[i][j] = 0.f; }

    const int aOff0 = (rowgrp * 32 + (lane & 15)) * ASTRIDE + ((lane >> 4) << 3);
    const int aOff1 = aOff0 + 16 * ASTRIDE;
    const uint32_t aHB = su(Ah), aLB = su(Al);
    const int bRowK = (lane & 7) + (((lane >> 3) & 1) << 3);
    const int bColN = (half << 6) + ((lane >> 4) << 3);
    const uint32_t bHB = su(Bh), bLB = su(Bl);

    for (int k0 = 0; k0 < 128; k0 += 16) {
        uint32_t a0h0, a0h1, a0h2, a0h3, a0l0, a0l1, a0l2, a0l3;
        uint32_t a1h0, a1h1, a1h2, a1h3, a1l0, a1l1, a1l2, a1l3;
        LDSM_X4(a0h0, a0h1, a0h2, a0h3, aHB + 2u * (aOff0 + k0));
        LDSM_X4(a0l0, a0l1, a0l2, a0l3, aLB + 2u * (aOff0 + k0));
        LDSM_X4(a1h0, a1h1, a1h2, a1h3, aHB + 2u * (aOff1 + k0));
        LDSM_X4(a1l0, a1l1, a1l2, a1l3, aLB + 2u * (aOff1 + k0));
        const int bKOff = (bRowK + k0) * ASTRIDE + bColN;
#pragma unroll
        for (int nt2 = 0; nt2 < 4; nt2++) {
            const int n0 = nt2 * 16;
            uint32_t bh0, bh1, bh2, bh3, bl0, bl1, bl2, bl3;
            LDSM_X4T(bh0, bh1, bh2, bh3, bHB + 2u * (bKOff + n0));
            LDSM_X4T(bl0, bl1, bl2, bl3, bLB + 2u * (bKOff + n0));
            // rowblock 0
            MMA16816(acc0[2 * nt2],     a0h0, a0h1, a0h2, a0h3, bh0, bh1);
            MMA16816(acc0[2 * nt2],     a0h0, a0h1, a0h2, a0h3, bl0, bl1);
            MMA16816(acc0[2 * nt2],     a0l0, a0l1, a0l2, a0l3, bh0, bh1);
            MMA16816(acc0[2 * nt2 + 1], a0h0, a0h1, a0h2, a0h3, bh2, bh3);
            MMA16816(acc0[2 * nt2 + 1], a0h0, a0h1, a0h2, a0h3, bl2, bl3);
            MMA16816(acc0[2 * nt2 + 1], a0l0, a0l1, a0l2, a0l3, bh2, bh3);
            // rowblock 1
            MMA16816(acc1[2 * nt2],     a1h0, a1h1, a1h2, a1h3, bh0, bh1);
            MMA16816(acc1[2 * nt2],     a1h0, a1h1, a1h2, a1h3, bl0, bl1);
            MMA16816(acc1[2 * nt2],     a1l0, a1l1, a1l2, a1l3, bh0, bh1);
            MMA16816(acc1[2 * nt2 + 1], a1h0, a1h1, a1h2, a1h3, bh2, bh3);
            MMA16816(acc1[2 * nt2 + 1], a1h0, a1h1, a1h2, a1h3, bl2, bl3);
            MMA16816(acc1[2 * nt2 + 1], a1l0, a1l1, a1l2, a1l3, bh2, bh3);
        }
    }

    // ---- epilogue ----
    // thread owns rows: rb0: rA = rowgrp*32 + lane>>2, rB = rA+8 ; rb1: +16
    // cols: c = half*64 + nt*8 + (lane&3)*2 + {0,1}
    const int rA = rowgrp * 32 + (lane >> 2);
    const int cbase = (half << 6) + (lane & 3) * 2;
    const float inv = 1.f / 128.f;

    float rowS[4] = {0.f, 0.f, 0.f, 0.f};
    float rowSS[4] = {0.f, 0.f, 0.f, 0.f};
    // GCN combine + accumulate sums; store combined values back into acc
#pragma unroll
    for (int rb = 0; rb < 2; rb++) {
        float (*acc)[4] = rb ? acc1 : acc0;
#pragma unroll
        for (int sub = 0; sub < 2; sub++) {        // sub=0 -> row rA, sub=1 -> row rA+8
            const int r = rA + rb * 16 + sub * 8;
            const int rg = row0 + r;
            float dv = 1.f, d2 = 1.f;
            const bool small = (rg < NN);
            if (small) { dv = d_dinv[rg]; d2 = dv * dv; }
            float s = 0.f, ss = 0.f;
#pragma unroll
            for (int nt = 0; nt < 8; nt++) {
                const int c = cbase + nt * 8;
                float2 sv = make_float2(0.f, 0.f);
                if (small) sv = *reinterpret_cast<const float2*>(&d_S2[rg * CC + c]);
                float v0 = fmaf(acc[nt][2 * sub + 0], d2, fmaf(dv, sv.x, sb2[c]));
                float v1 = fmaf(acc[nt][2 * sub + 1], d2, fmaf(dv, sv.y, sb2[c + 1]));
                acc[nt][2 * sub + 0] = v0;
                acc[nt][2 * sub + 1] = v1;
                s += v0 + v1;
                ss += v0 * v0 + v1 * v1;
            }
            rowS[rb * 2 + sub] = s;
            rowSS[rb * 2 + sub] = ss;
        }
    }
#pragma unroll
    for (int o = 1; o <= 2; o <<= 1) {
#pragma unroll
        for (int i = 0; i < 4; i++) {
            rowS[i]  += __shfl_xor_sync(0xffffffffu, rowS[i],  o);
            rowSS[i] += __shfl_xor_sync(0xffffffffu, rowSS[i], o);
        }
    }
    if ((lane & 3) == 0) {
#pragma unroll
        for (int i = 0; i < 4; i++) {
            int r = rA + (i >> 1) * 16 + (i & 1) * 8;
            redS[half][r] = rowS[i];
            redSS[half][r] = rowSS[i];
        }
    }
    __syncthreads();

    float dot[4] = {0.f, 0.f, 0.f, 0.f};
#pragma unroll
    for (int rb = 0; rb < 2; rb++) {
        float (*acc)[4] = rb ? acc1 : acc0;
#pragma unroll
        for (int sub = 0; sub < 2; sub++) {
            const int r = rA + rb * 16 + sub * 8;
            float st = redS[0][r] + redS[1][r];
            float sst = redSS[0][r] + redSS[1][r];
            float mu = st * inv;
            float rstd = rsqrtf(sst * inv - mu * mu + EPSV);
            float dloc = 0.f;
#pragma unroll
            for (int nt = 0; nt < 8; nt++) {
                const int c = cbase + nt * 8;
                float y0 = fmaf((acc[nt][2 * sub + 0] - mu) * rstd, slg[c],     slb[c]);
                float y1 = fmaf((acc[nt][2 * sub + 1] - mu) * rstd, slg[c + 1], slb[c + 1]);
                dloc = fmaf(fmaxf(y0, 0.f), sw3[c],     dloc);
                dloc = fmaf(fmaxf(y1, 0.f), sw3[c + 1], dloc);
            }
            dot[rb * 2 + sub] = dloc;
        }
    }
#pragma unroll
    for (int o = 1; o <= 2; o <<= 1)
#pragma unroll
        for (int i = 0; i < 4; i++)
            dot[i] += __shfl_xor_sync(0xffffffffu, dot[i], o);

    if ((lane & 3) == 0) {
#pragma unroll
        for (int i = 0; i < 4; i++) {
            int r = rA + (i >> 1) * 16 + (i & 1) * 8;
            redD[half][r] = dot[i];
        }
    }
    __syncthreads();
    // write: half 0, lane&3==0 threads own 4 rows each
    if (half == 0 && (lane & 3) == 0) {
        const float b3v = b3[0];
#pragma unroll
        for (int i = 0; i < 4; i++) {
            int r = rA + (i >> 1) * 16 + (i & 1) * 8;
            out[row0 + r] = redD[0][r] + redD[1][r] + b3v;
        }
    }
}

// -------------------- launch --------------------
extern "C" void kernel_launch(void* const* d_in, const int* in_sizes, int n_in,
                              void* d_out, int out_size) {
    const float* x    = (const float*)d_in[0];
    const int*   ei32 = (const int*)d_in[1];
    const float* W1   = (const float*)d_in[2];
    const float* b1   = (const float*)d_in[3];
    const float* bn_g = (const float*)d_in[4];
    const float* bn_b = (const float*)d_in[5];
    const float* W2   = (const float*)d_in[6];
    const float* b2   = (const float*)d_in[7];
    const float* ln_g = (const float*)d_in[8];
    const float* ln_b = (const float*)d_in[9];
    const float* W3   = (const float*)d_in[10];
    const float* b3   = (const float*)d_in[11];
    float* out = (float*)d_out;

    const int FIN_SMEM = 4 * 128 * ASTRIDE * 2;   // 139,264 B
    cudaFuncSetAttribute(k_final, cudaFuncAttributeMaxDynamicSharedMemorySize, FIN_SMEM);

    k_zero<<<256, 256>>>();
    k_detect<<<1, 32>>>(ei32);
    k_prepw<<<64, 256>>>(W2);
    k_convert<<<1024, 256>>>(ei32);
    k_dinv<<<(NN + 255) / 256, 256>>>();
    k_scan<<<1, 1024>>>();
    k_fill<<<(EE + 255) / 256, 256>>>();
    k_pq<<<dim3((NN + 127) / 128, 2), 256>>>(x, W1);
    k_w0<<<NN, CC>>>();
    k_gather<0><<<NN, CC>>>();
    k_stats<<<EE / 512, CC>>>(b1);
    k_bnfinal<<<1, CC>>>(bn_g, bn_b, b1);
    k_g2small<<<(NN + 127) / 128, 256>>>(W2);
    k_gather<1><<<NN, CC>>>();
    k_final<<<EE / 128, 256, FIN_SMEM>>>(b2, ln_g, ln_b, W3, b3, out);
}

// round 10
// speedup vs baseline: 1.4017x; 1.0108x over previous
#include <cuda_runtime.h>
#include <cuda_bf16.h>
#include <stdint.h>
#include <math.h>

#define NN 20000
#define EE 640000
#define CC 128
#define EPSV 1e-5f
#define ASTRIDE 136

// -------------------- scratch (device globals; no allocation) --------------------
__device__ __align__(16) float  d_PQ[NN * 256];   // [node][0:128]=P, [128:256]=Q (20MB, L2-resident)
__device__ __align__(16) float  d_W0[NN * CC];
__device__ __align__(16) float  d_S1[NN * CC];
__device__ __align__(16) float  d_S2[NN * CC];    // first SP (stats), later real S2
__device__ __align__(16) __nv_bfloat16 d_Bh[128 * ASTRIDE];
__device__ __align__(16) __nv_bfloat16 d_Bl[128 * ASTRIDE];
__device__ int    d_src[EE];
__device__ int    d_dst[EE];
__device__ int    d_is64;
__device__ int    d_cnt[NN];      // indeg
__device__ int    d_ocnt[NN];     // outdeg
__device__ int    d_start[NN + 1];
__device__ int    d_cursor[NN];
__device__ int    d_srcs[EE];
__device__ float  d_dinv[NN];
__device__ double d_sum[CC];
__device__ double d_sumsq[CC];
__device__ float  d_bnA[CC];
__device__ float  d_bnB[CC];

// -------------------- dtype detect --------------------
__global__ void k_detect(const int* __restrict__ ei32) {
    if (threadIdx.x == 0) {
        int orv = 0;
        for (int i = 0; i < 128; i++) orv |= ei32[2 * i + 1];
        d_is64 = (orv == 0) ? 1 : 0;
    }
}

__global__ void k_zero() {
    int i = blockIdx.x * blockDim.x + threadIdx.x;
    int stride = gridDim.x * blockDim.x;
    for (int j = i; j < NN; j += stride) { d_cnt[j] = 0; d_ocnt[j] = 0; }
    if (i < CC) { d_sum[i] = 0.0; d_sumsq[i] = 0.0; }
}

__global__ void k_convert(const int* __restrict__ ei32) {
    const int is64 = d_is64;
    int i = blockIdx.x * blockDim.x + threadIdx.x;
    int stride = gridDim.x * blockDim.x;
    for (int e = i; e < EE; e += stride) {
        int s, d;
        if (is64) { s = ei32[2 * e]; d = ei32[2 * (EE + e)]; }
        else      { s = ei32[e];     d = ei32[EE + e]; }
        d_src[e] = s;
        d_dst[e] = d;
        atomicAdd(&d_cnt[d], 1);
        atomicAdd(&d_ocnt[s], 1);
    }
}

__global__ void k_dinv() {
    int i = blockIdx.x * blockDim.x + threadIdx.x;
    if (i < NN) d_dinv[i] = rsqrtf(1.0f + (float)d_cnt[i]);
}

__global__ void k_scan() {
    __shared__ int sh[1024];
    __shared__ int carry_s;
    const int tid = threadIdx.x;
    if (tid == 0) carry_s = 0;
    __syncthreads();
    for (int base = 0; base < NN; base += 1024) {
        int idx = base + tid;
        int v = (idx < NN) ? d_cnt[idx] : 0;
        sh[tid] = v;
        __syncthreads();
        for (int o = 1; o < 1024; o <<= 1) {
            int t = (tid >= o) ? sh[tid - o] : 0;
            __syncthreads();
            sh[tid] += t;
            __syncthreads();
        }
        int excl = sh[tid] - v + carry_s;
        if (idx < NN) { d_start[idx] = excl; d_cursor[idx] = excl; }
        __syncthreads();
        if (tid == 0) carry_s += sh[1023];
        __syncthreads();
    }
    if (tid == 0) d_start[NN] = carry_s;
}

__global__ void k_fill() {
    int e = blockIdx.x * blockDim.x + threadIdx.x;
    if (e < EE) {
        int d = d_dst[e];
        int pos = atomicAdd(&d_cursor[d], 1);
        d_srcs[pos] = d_src[e];
    }
}

// -------------------- W2 pre-split into padded hi/lo bf16 --------------------
__global__ void k_prepw(const float* __restrict__ W2) {
    int idx = blockIdx.x * blockDim.x + threadIdx.x;   // 16384
    int k = idx >> 7, n = idx & 127;
    float v = W2[(size_t)k * 128 + n];
    __nv_bfloat16 h = __float2bfloat16_rn(v);
    __nv_bfloat16 l = __float2bfloat16_rn(v - __bfloat162float(h));
    d_Bh[k * ASTRIDE + n] = h;
    d_Bl[k * ASTRIDE + n] = l;
}

// -------------------- PQ = x @ [W1_top | W1_bot] --------------------
__global__ __launch_bounds__(256) void k_pq(const float* __restrict__ x,
                                            const float* __restrict__ W1) {
    __shared__ __align__(16) float As[16][128];
    __shared__ __align__(16) float Bs[16][128];
    const int tid = threadIdx.x;
    const int tx = tid & 15, ty = tid >> 4;
    const int row0 = blockIdx.x * 128;
    const int half = blockIdx.y;
    const int m = tid & 127;
    const int kh = (tid >> 7) * 8;
    const int kb = tid >> 4;
    const int n0 = (tid & 15) * 8;

    float acc[8][8];
#pragma unroll
    for (int i = 0; i < 8; i++)
#pragma unroll
        for (int j = 0; j < 8; j++) acc[i][j] = 0.f;

    for (int k0 = 0; k0 < 128; k0 += 16) {
        float4 a0 = make_float4(0, 0, 0, 0), a1 = make_float4(0, 0, 0, 0);
        int rr = row0 + m;
        if (rr < NN) {
            const float4* ap = reinterpret_cast<const float4*>(x + (size_t)rr * 128 + k0 + kh);
            a0 = ap[0]; a1 = ap[1];
        }
        As[kh + 0][m] = a0.x; As[kh + 1][m] = a0.y; As[kh + 2][m] = a0.z; As[kh + 3][m] = a0.w;
        As[kh + 4][m] = a1.x; As[kh + 5][m] = a1.y; As[kh + 6][m] = a1.z; As[kh + 7][m] = a1.w;

        const float4* bp = reinterpret_cast<const float4*>(
            W1 + (size_t)(half * 128 + k0 + kb) * 128 + n0);
        float4 b0 = bp[0], b1v = bp[1];
        *reinterpret_cast<float4*>(&Bs[kb][n0]) = b0;
        *reinterpret_cast<float4*>(&Bs[kb][n0 + 4]) = b1v;
        __syncthreads();
#pragma unroll
        for (int k = 0; k < 16; k++) {
            float a[8], b[8];
            *reinterpret_cast<float4*>(a)     = *reinterpret_cast<const float4*>(&As[k][ty * 8]);
            *reinterpret_cast<float4*>(a + 4) = *reinterpret_cast<const float4*>(&As[k][ty * 8 + 4]);
            *reinterpret_cast<float4*>(b)     = *reinterpret_cast<const float4*>(&Bs[k][tx * 8]);
            *reinterpret_cast<float4*>(b + 4) = *reinterpret_cast<const float4*>(&Bs[k][tx * 8 + 4]);
#pragma unroll
            for (int i = 0; i < 8; i++)
#pragma unroll
                for (int j = 0; j < 8; j++) acc[i][j] = fmaf(a[i], b[j], acc[i][j]);
        }
        __syncthreads();
    }
#pragma unroll
    for (int i = 0; i < 8; i++) {
        int r = row0 + ty * 8 + i;
        if (r < NN) {
            float4 o0 = make_float4(acc[i][0], acc[i][1], acc[i][2], acc[i][3]);
            float4 o1 = make_float4(acc[i][4], acc[i][5], acc[i][6], acc[i][7]);
            float* dst = &d_PQ[(size_t)r * 256 + half * 128 + tx * 8];
            reinterpret_cast<float4*>(dst)[0] = o0;
            reinterpret_cast<float4*>(dst)[1] = o1;
        }
    }
}

__global__ void k_w0() {
    int j = blockIdx.x;
    int c = threadIdx.x;
    int s = d_src[j];
    int d = d_dst[j];
    float dv = d_dinv[j];
    d_W0[j * CC + c] = (d_PQ[s * 256 + c] + d_PQ[d * 256 + 128 + c]) * dv;
}

// gather: PASS 0 -> S1 += W0[src]; PASS 1 -> S2 += W0[src]; PASS 2 -> S2 += P[src] (stats SP)
template <int PASS>
__global__ void k_gather() {
    float* S = (PASS == 0) ? d_S1 : d_S2;
    const int d = blockIdx.x;
    const int c = threadIdx.x;
    const int p0 = d_start[d], p1 = d_start[d + 1];
    float a0 = 0.f, a1 = 0.f, a2 = 0.f, a3 = 0.f;
    int p = p0;
    if (PASS == 2) {
        for (; p + 4 <= p1; p += 4) {
            a0 += d_PQ[d_srcs[p] * 256 + c];
            a1 += d_PQ[d_srcs[p + 1] * 256 + c];
            a2 += d_PQ[d_srcs[p + 2] * 256 + c];
            a3 += d_PQ[d_srcs[p + 3] * 256 + c];
        }
        for (; p < p1; p++) a0 += d_PQ[d_srcs[p] * 256 + c];
    } else {
        for (; p + 4 <= p1; p += 4) {
            a0 += d_W0[d_srcs[p] * CC + c];
            a1 += d_W0[d_srcs[p + 1] * CC + c];
            a2 += d_W0[d_srcs[p + 2] * CC + c];
            a3 += d_W0[d_srcs[p + 3] * CC + c];
        }
        for (; p < p1; p++) a0 += d_W0[d_srcs[p] * CC + c];
    }
    S[d * CC + c] = (a0 + a1) + (a2 + a3);
}

// -------------------- BN stats via node-level algebra --------------------
// sum_e h0_e = sum_n od*P + id*Q' ;  sum_e h0_e^2 = sum_n od*P^2 + id*Q'^2 + 2*Q'*SP
// (Q' = Q + b1; SP in d_S2)
__global__ void k_stats2(const float* __restrict__ b1) {
    const int c = threadIdx.x;
    const int n0 = blockIdx.x * 128;
    const float b1c = b1[c];
    float s = 0.f, ss = 0.f;
    for (int i = 0; i < 128; i++) {
        int n = n0 + i;
        if (n < NN) {
            float od = (float)d_ocnt[n];
            float id = (float)d_cnt[n];
            float pv = d_PQ[n * 256 + c];
            float qv = d_PQ[n * 256 + 128 + c] + b1c;
            float sp = d_S2[n * CC + c];
            s += od * pv + id * qv;
            ss += od * pv * pv + id * qv * qv + 2.f * qv * sp;
        }
    }
    atomicAdd(&d_sum[c], (double)s);
    atomicAdd(&d_sumsq[c], (double)ss);
}

// corrections for edge-rows j < NN: true h uses GCN terms
__global__ void k_statsE(const float* __restrict__ b1) {
    const int c = threadIdx.x;
    const int j0 = blockIdx.x * 128;
    const float b1c = b1[c];
    float s = 0.f, ss = 0.f;
    for (int i = 0; i < 128; i++) {
        int j = j0 + i;
        if (j < NN) {
            int sN = d_src[j], dN = d_dst[j];
            float dv = d_dinv[j];
            float h0 = d_PQ[sN * 256 + c] + d_PQ[dN * 256 + 128 + c];
            float naive = h0 + b1c;
            float tru = fmaf(h0, dv * dv, fmaf(dv, d_S1[j * CC + c], b1c));
            s += tru - naive;
            ss += tru * tru - naive * naive;
        }
    }
    atomicAdd(&d_sum[c], (double)s);
    atomicAdd(&d_sumsq[c], (double)ss);
}

__global__ void k_bnfinal(const float* __restrict__ bn_g, const float* __restrict__ bn_b,
                          const float* __restrict__ b1) {
    int c = threadIdx.x;
    double mu = d_sum[c] / (double)EE;
    double var = d_sumsq[c] / (double)EE - mu * mu;
    float rstd = rsqrtf((float)var + EPSV);
    float a = bn_g[c] * rstd;
    d_bnA[c] = a;
    d_bnB[c] = fmaf(b1[c], a, fmaf(-(float)mu, a, bn_b[c]));
}

// ========== fp32 A-tile builder (for g2small only) ====
__device__ __forceinline__ void build_a_tile(
    float As[16][128], const int* ssrc, const int* sdst, const float* sdv,
    const float* sA, const float* sB, int row0, int m, int kh, int k0) {
    const int s = ssrc[m], d = sdst[m];
    const float dv = sdv[m];
    const float4* pp = reinterpret_cast<const float4*>(&d_PQ[s * 256 + k0 + kh]);
    float4 p0 = pp[0], p1 = pp[1];
    const float4* qp = reinterpret_cast<const float4*>(&d_PQ[d * 256 + 128 + k0 + kh]);
    float4 q0 = qp[0], q1 = qp[1];
    float h[8] = {p0.x + q0.x, p0.y + q0.y, p0.z + q0.z, p0.w + q0.w,
                  p1.x + q1.x, p1.y + q1.y, p1.z + q1.z, p1.w + q1.w};
    if (dv >= 0.f) {
        const float4* s1p = reinterpret_cast<const float4*>(&d_S1[(row0 + m) * CC + k0 + kh]);
        float4 t0 = s1p[0], t1 = s1p[1];
        float sv[8] = {t0.x, t0.y, t0.z, t0.w, t1.x, t1.y, t1.z, t1.w};
        float dv2 = dv * dv;
#pragma unroll
        for (int t = 0; t < 8; t++) h[t] = fmaf(h[t], dv2, dv * sv[t]);
    }
#pragma unroll
    for (int t = 0; t < 8; t++) {
        int kk = k0 + kh + t;
        As[kh + t][m] = fmaxf(fmaf(h[t], sA[kk], sB[kk]), 0.f);
    }
}

// -------------------- g2small (fp32, rows < NN only) --------------------
__global__ __launch_bounds__(256) void k_g2small(const float* __restrict__ W2) {
    __shared__ __align__(16) float As[16][128];
    __shared__ __align__(16) float Bs[16][128];
    __shared__ int ssrc[128], sdst[128];
    __shared__ float sdv[128], sA[128], sB[128];
    const int tid = threadIdx.x;
    const int tx = tid & 15, ty = tid >> 4;
    const int row0 = blockIdx.x * 128;
    const int m = tid & 127;
    const int kh = (tid >> 7) * 8;
    const int kb = tid >> 4;
    const int n0 = (tid & 15) * 8;

    if (tid < 128) {
        int rr = row0 + tid;
        ssrc[tid] = d_src[rr];
        sdst[tid] = d_dst[rr];
        sdv[tid] = (rr < NN) ? d_dinv[rr] : -1.f;
        sA[tid] = d_bnA[tid];
        sB[tid] = d_bnB[tid];
    }
    __syncthreads();

    float acc[8][8];
#pragma unroll
    for (int i = 0; i < 8; i++)
#pragma unroll
        for (int j = 0; j < 8; j++) acc[i][j] = 0.f;

    for (int k0 = 0; k0 < 128; k0 += 16) {
        build_a_tile(As, ssrc, sdst, sdv, sA, sB, row0, m, kh, k0);
        const float4* bp = reinterpret_cast<const float4*>(
            W2 + (size_t)(k0 + kb) * 128 + n0);
        float4 b0 = bp[0], b1v = bp[1];
        *reinterpret_cast<float4*>(&Bs[kb][n0]) = b0;
        *reinterpret_cast<float4*>(&Bs[kb][n0 + 4]) = b1v;
        __syncthreads();
#pragma unroll
        for (int k = 0; k < 16; k++) {
            float a[8], b[8];
            *reinterpret_cast<float4*>(a)     = *reinterpret_cast<const float4*>(&As[k][ty * 8]);
            *reinterpret_cast<float4*>(a + 4) = *reinterpret_cast<const float4*>(&As[k][ty * 8 + 4]);
            *reinterpret_cast<float4*>(b)     = *reinterpret_cast<const float4*>(&Bs[k][tx * 8]);
            *reinterpret_cast<float4*>(b + 4) = *reinterpret_cast<const float4*>(&Bs[k][tx * 8 + 4]);
#pragma unroll
            for (int i = 0; i < 8; i++)
#pragma unroll
                for (int j = 0; j < 8; j++) acc[i][j] = fmaf(a[i], b[j], acc[i][j]);
        }
        __syncthreads();
    }
#pragma unroll
    for (int i = 0; i < 8; i++) {
        int r = row0 + ty * 8 + i;
        if (r < NN) {
            float dv = d_dinv[r];
            float4 o0 = make_float4(acc[i][0] * dv, acc[i][1] * dv, acc[i][2] * dv, acc[i][3] * dv);
            float4 o1 = make_float4(acc[i][4] * dv, acc[i][5] * dv, acc[i][6] * dv, acc[i][7] * dv);
            float* dst = &d_W0[r * CC + tx * 8];
            reinterpret_cast<float4*>(dst)[0] = o0;
            reinterpret_cast<float4*>(dst)[1] = o1;
        }
    }
}

// ==================== k_final: split-bf16 mma.sync, 4 tiles per CTA ====================
__device__ __forceinline__ uint32_t su(const void* p) {
    return (uint32_t)__cvta_generic_to_shared(p);
}
__device__ __forceinline__ void split2(float v0, float v1, uint32_t& hi, uint32_t& lo) {
    __nv_bfloat16 h0 = __float2bfloat16_rn(v0), h1 = __float2bfloat16_rn(v1);
    float l0f = v0 - __bfloat162float(h0);
    float l1f = v1 - __bfloat162float(h1);
    __nv_bfloat16 l0 = __float2bfloat16_rn(l0f), l1 = __float2bfloat16_rn(l1f);
    hi = ((uint32_t)__bfloat16_as_ushort(h1) << 16) | (uint32_t)__bfloat16_as_ushort(h0);
    lo = ((uint32_t)__bfloat16_as_ushort(l1) << 16) | (uint32_t)__bfloat16_as_ushort(l0);
}

#define LDSM_X4(r0, r1, r2, r3, addr)                                              \
    asm volatile("ldmatrix.sync.aligned.m8n8.x4.shared.b16 {%0,%1,%2,%3},[%4];"    \
                 : "=r"(r0), "=r"(r1), "=r"(r2), "=r"(r3) : "r"(addr))
#define LDSM_X4T(r0, r1, r2, r3, addr)                                                  \
    asm volatile("ldmatrix.sync.aligned.m8n8.x4.trans.shared.b16 {%0,%1,%2,%3},[%4];"   \
                 : "=r"(r0), "=r"(r1), "=r"(r2), "=r"(r3) : "r"(addr))
#define MMA16816(d, a0, a1, a2, a3, b0, b1)                                             \
    asm volatile("mma.sync.aligned.m16n8k16.row.col.f32.bf16.bf16.f32 "                 \
                 "{%0,%1,%2,%3},{%4,%5,%6,%7},{%8,%9},{%0,%1,%2,%3};"                   \
                 : "+f"(d[0]), "+f"(d[1]), "+f"(d[2]), "+f"(d[3])                       \
                 : "r"(a0), "r"(a1), "r"(a2), "r"(a3), "r"(b0), "r"(b1))

__global__ __launch_bounds__(256) void k_final(const float* __restrict__ b2,
                                               const float* __restrict__ lng,
                                               const float* __restrict__ lnb,
                                               const float* __restrict__ W3,
                                               const float* __restrict__ b3,
                                               float* __restrict__ out) {
    extern __shared__ __align__(16) char dynsmem[];
    __nv_bfloat16* Ah = (__nv_bfloat16*)dynsmem;          // [128][ASTRIDE]
    __nv_bfloat16* Al = Ah + 128 * ASTRIDE;
    __nv_bfloat16* Bh = Al + 128 * ASTRIDE;               // [128 k][ASTRIDE n]
    __nv_bfloat16* Bl = Bh + 128 * ASTRIDE;

    __shared__ float sA[128], sB[128], sb2[128], slg[128], slb[128], sw3[128];
    __shared__ float redS[2][128], redSS[2][128], redD[2][128];

    const int tid = threadIdx.x;
    const int lane = tid & 31;
    const int w = tid >> 5;
    const int base = blockIdx.x * 512;

    if (tid < 128) {
        sA[tid] = d_bnA[tid];
        sB[tid] = d_bnB[tid];
        sb2[tid] = b2[tid];
        slg[tid] = lng[tid];
        slb[tid] = lnb[tid];
        sw3[tid] = W3[tid];
    }

    // ---- copy pre-split, padded B once ----
    {
        const uint4* gh = reinterpret_cast<const uint4*>(d_Bh);
        const uint4* gl = reinterpret_cast<const uint4*>(d_Bl);
        uint4* sh = reinterpret_cast<uint4*>(Bh);
        uint4* sl = reinterpret_cast<uint4*>(Bl);
        for (int i = tid; i < 2176; i += 256) {
            sh[i] = gh[i];
            sl[i] = gl[i];
        }
    }
    __syncthreads();

    const int rowgrp = w & 3;
    const int half = w >> 2;
    const int arow = tid >> 1;
    const int kh = (tid & 1) * 64;
    const int aOff0 = (rowgrp * 32 + (lane & 15)) * ASTRIDE + ((lane >> 4) << 3);
    const int aOff1 = aOff0 + 16 * ASTRIDE;
    const uint32_t aHB = su(Ah), aLB = su(Al);
    const int bRowK = (lane & 7) + (((lane >> 3) & 1) << 3);
    const int bColN = (half << 6) + ((lane >> 4) << 3);
    const uint32_t bHB = su(Bh), bLB = su(Bl);
    const int rA = rowgrp * 32 + (lane >> 2);
    const int cbase = (half << 6) + (lane & 3) * 2;
    const float inv = 1.f / 128.f;

    for (int t = 0; t < 4; t++) {
        const int row0 = base + t * 128;

        // ---- build A tile ----
        {
            const int r = row0 + arow;
            const int s = d_src[r], d = d_dst[r];
            const float dv = (r < NN) ? d_dinv[r] : -1.f;
            const float dv2 = dv * dv;
            const float4* pp = reinterpret_cast<const float4*>(&d_PQ[s * 256 + kh]);
            const float4* qp = reinterpret_cast<const float4*>(&d_PQ[d * 256 + 128 + kh]);
            const float4* s1p = reinterpret_cast<const float4*>(&d_S1[r * CC + kh]);
            uint32_t* ahp = reinterpret_cast<uint32_t*>(&Ah[arow * ASTRIDE + kh]);
            uint32_t* alp = reinterpret_cast<uint32_t*>(&Al[arow * ASTRIDE + kh]);
#pragma unroll 4
            for (int i = 0; i < 16; i++) {
                float4 p = pp[i], q = qp[i];
                float h0 = p.x + q.x, h1 = p.y + q.y, h2 = p.z + q.z, h3 = p.w + q.w;
                if (dv >= 0.f) {
                    float4 tt = s1p[i];
                    h0 = fmaf(h0, dv2, dv * tt.x);
                    h1 = fmaf(h1, dv2, dv * tt.y);
                    h2 = fmaf(h2, dv2, dv * tt.z);
                    h3 = fmaf(h3, dv2, dv * tt.w);
                }
                int c = kh + 4 * i;
                float v0 = fmaxf(fmaf(h0, sA[c + 0], sB[c + 0]), 0.f);
                float v1 = fmaxf(fmaf(h1, sA[c + 1], sB[c + 1]), 0.f);
                float v2 = fmaxf(fmaf(h2, sA[c + 2], sB[c + 2]), 0.f);
                float v3 = fmaxf(fmaf(h3, sA[c + 3], sB[c + 3]), 0.f);
                uint32_t hi0, lo0, hi1, lo1;
                split2(v0, v1, hi0, lo0);
                split2(v2, v3, hi1, lo1);
                ahp[2 * i] = hi0; ahp[2 * i + 1] = hi1;
                alp[2 * i] = lo0; alp[2 * i + 1] = lo1;
            }
        }
        __syncthreads();

        // ---- mma ----
        float acc0[8][4], acc1[8][4];
#pragma unroll
        for (int i = 0; i < 8; i++)
#pragma unroll
            for (int j = 0; j < 4; j++) { acc0[i][j] = 0.f; acc1[i][j] = 0.f; }

        for (int k0 = 0; k0 < 128; k0 += 16) {
            uint32_t a0h0, a0h1, a0h2, a0h3, a0l0, a0l1, a0l2, a0l3;
            uint32_t a1h0, a1h1, a1h2, a1h3, a1l0, a1l1, a1l2, a1l3;
            LDSM_X4(a0h0, a0h1, a0h2, a0h3, aHB + 2u * (aOff0 + k0));
            LDSM_X4(a0l0, a0l1, a0l2, a0l3, aLB + 2u * (aOff0 + k0));
            LDSM_X4(a1h0, a1h1, a1h2, a1h3, aHB + 2u * (aOff1 + k0));
            LDSM_X4(a1l0, a1l1, a1l2, a1l3, aLB + 2u * (aOff1 + k0));
            const int bKOff = (bRowK + k0) * ASTRIDE + bColN;
#pragma unroll
            for (int nt2 = 0; nt2 < 4; nt2++) {
                const int n0 = nt2 * 16;
                uint32_t bh0, bh1, bh2, bh3, bl0, bl1, bl2, bl3;
                LDSM_X4T(bh0, bh1, bh2, bh3, bHB + 2u * (bKOff + n0));
                LDSM_X4T(bl0, bl1, bl2, bl3, bLB + 2u * (bKOff + n0));
                MMA16816(acc0[2 * nt2],     a0h0, a0h1, a0h2, a0h3, bh0, bh1);
                MMA16816(acc0[2 * nt2],     a0h0, a0h1, a0h2, a0h3, bl0, bl1);
                MMA16816(acc0[2 * nt2],     a0l0, a0l1, a0l2, a0l3, bh0, bh1);
                MMA16816(acc0[2 * nt2 + 1], a0h0, a0h1, a0h2, a0h3, bh2, bh3);
                MMA16816(acc0[2 * nt2 + 1], a0h0, a0h1, a0h2, a0h3, bl2, bl3);
                MMA16816(acc0[2 * nt2 + 1], a0l0, a0l1, a0l2, a0l3, bh2, bh3);
                MMA16816(acc1[2 * nt2],     a1h0, a1h1, a1h2, a1h3, bh0, bh1);
                MMA16816(acc1[2 * nt2],     a1h0, a1h1, a1h2, a1h3, bl0, bl1);
                MMA16816(acc1[2 * nt2],     a1l0, a1l1, a1l2, a1l3, bh0, bh1);
                MMA16816(acc1[2 * nt2 + 1], a1h0, a1h1, a1h2, a1h3, bh2, bh3);
                MMA16816(acc1[2 * nt2 + 1], a1h0, a1h1, a1h2, a1h3, bl2, bl3);
                MMA16816(acc1[2 * nt2 + 1], a1l0, a1l1, a1l2, a1l3, bh2, bh3);
            }
        }

        // ---- epilogue ----
        float rowS[4] = {0.f, 0.f, 0.f, 0.f};
        float rowSS[4] = {0.f, 0.f, 0.f, 0.f};
#pragma unroll
        for (int rb = 0; rb < 2; rb++) {
            float (*acc)[4] = rb ? acc1 : acc0;
#pragma unroll
            for (int sub = 0; sub < 2; sub++) {
                const int r = rA + rb * 16 + sub * 8;
                const int rg = row0 + r;
                float dv = 1.f, d2 = 1.f;
                const bool small = (rg < NN);
                if (small) { dv = d_dinv[rg]; d2 = dv * dv; }
                float s = 0.f, ss = 0.f;
#pragma unroll
                for (int nt = 0; nt < 8; nt++) {
                    const int c = cbase + nt * 8;
                    float2 sv = make_float2(0.f, 0.f);
                    if (small) sv = *reinterpret_cast<const float2*>(&d_S2[rg * CC + c]);
                    float v0 = fmaf(acc[nt][2 * sub + 0], d2, fmaf(dv, sv.x, sb2[c]));
                    float v1 = fmaf(acc[nt][2 * sub + 1], d2, fmaf(dv, sv.y, sb2[c + 1]));
                    acc[nt][2 * sub + 0] = v0;
                    acc[nt][2 * sub + 1] = v1;
                    s += v0 + v1;
                    ss += v0 * v0 + v1 * v1;
                }
                rowS[rb * 2 + sub] = s;
                rowSS[rb * 2 + sub] = ss;
            }
        }
#pragma unroll
        for (int o = 1; o <= 2; o <<= 1) {
#pragma unroll
            for (int i = 0; i < 4; i++) {
                rowS[i]  += __shfl_xor_sync(0xffffffffu, rowS[i],  o);
                rowSS[i] += __shfl_xor_sync(0xffffffffu, rowSS[i], o);
            }
        }
        if ((lane & 3) == 0) {
#pragma unroll
            for (int i = 0; i < 4; i++) {
                int r = rA + (i >> 1) * 16 + (i & 1) * 8;
                redS[half][r] = rowS[i];
                redSS[half][r] = rowSS[i];
            }
        }
        __syncthreads();

        float dot[4] = {0.f, 0.f, 0.f, 0.f};
#pragma unroll
        for (int rb = 0; rb < 2; rb++) {
            float (*acc)[4] = rb ? acc1 : acc0;
#pragma unroll
            for (int sub = 0; sub < 2; sub++) {
                const int r = rA + rb * 16 + sub * 8;
                float st = redS[0][r] + redS[1][r];
                float sst = redSS[0][r] + redSS[1][r];
                float mu = st * inv;
                float rstd = rsqrtf(sst * inv - mu * mu + EPSV);
                float dloc = 0.f;
#pragma unroll
                for (int nt = 0; nt < 8; nt++) {
                    const int c = cbase + nt * 8;
                    float y0 = fmaf((acc[nt][2 * sub + 0] - mu) * rstd, slg[c],     slb[c]);
                    float y1 = fmaf((acc[nt][2 * sub + 1] - mu) * rstd, slg[c + 1], slb[c + 1]);
                    dloc = fmaf(fmaxf(y0, 0.f), sw3[c],     dloc);
                    dloc = fmaf(fmaxf(y1, 0.f), sw3[c + 1], dloc);
                }
                dot[rb * 2 + sub] = dloc;
            }
        }
#pragma unroll
        for (int o = 1; o <= 2; o <<= 1)
#pragma unroll
            for (int i = 0; i < 4; i++)
                dot[i] += __shfl_xor_sync(0xffffffffu, dot[i], o);

        if ((lane & 3) == 0) {
#pragma unroll
            for (int i = 0; i < 4; i++) {
                int r = rA + (i >> 1) * 16 + (i & 1) * 8;
                redD[half][r] = dot[i];
            }
        }
        __syncthreads();
        if (half == 0 && (lane & 3) == 0) {
            const float b3v = b3[0];
#pragma unroll
            for (int i = 0; i < 4; i++) {
                int r = rA + (i >> 1) * 16 + (i & 1) * 8;
                out[row0 + r] = redD[0][r] + redD[1][r] + b3v;
            }
        }
        __syncthreads();
    }
}

// -------------------- launch --------------------
extern "C" void kernel_launch(void* const* d_in, const int* in_sizes, int n_in,
                              void* d_out, int out_size) {
    const float* x    = (const float*)d_in[0];
    const int*   ei32 = (const int*)d_in[1];
    const float* W1   = (const float*)d_in[2];
    const float* b1   = (const float*)d_in[3];
    const float* bn_g = (const float*)d_in[4];
    const float* bn_b = (const float*)d_in[5];
    const float* W2   = (const float*)d_in[6];
    const float* b2   = (const float*)d_in[7];
    const float* ln_g = (const float*)d_in[8];
    const float* ln_b = (const float*)d_in[9];
    const float* W3   = (const float*)d_in[10];
    const float* b3   = (const float*)d_in[11];
    float* out = (float*)d_out;

    const int FIN_SMEM = 4 * 128 * ASTRIDE * 2;   // 139,264 B
    cudaFuncSetAttribute(k_final, cudaFuncAttributeMaxDynamicSharedMemorySize, FIN_SMEM);

    k_zero<<<256, 256>>>();
    k_detect<<<1, 32>>>(ei32);
    k_prepw<<<64, 256>>>(W2);
    k_convert<<<1024, 256>>>(ei32);
    k_dinv<<<(NN + 255) / 256, 256>>>();
    k_scan<<<1, 1024>>>();
    k_fill<<<(EE + 255) / 256, 256>>>();
    k_pq<<<dim3((NN + 127) / 128, 2), 256>>>(x, W1);
    k_w0<<<NN, CC>>>();
    k_gather<0><<<NN, CC>>>();              // S1
    k_gather<2><<<NN, CC>>>();              // SP into d_S2 (stats only)
    k_stats2<<<(NN + 127) / 128, CC>>>(b1);
    k_statsE<<<(NN + 127) / 128, CC>>>(b1);
    k_bnfinal<<<1, CC>>>(bn_g, bn_b, b1);
    k_g2small<<<(NN + 127) / 128, 256>>>(W2);
    k_gather<1><<<NN, CC>>>();              // real S2 (overwrites SP)
    k_final<<<EE / 512, 256, FIN_SMEM>>>(b2, ln_g, ln_b, W3, b3, out);
}